// round 9
// baseline (speedup 1.0000x reference)
#include <cuda_runtime.h>
#include <cuda_bf16.h>
#include <cstdint>

#define DEVFN __device__ __forceinline__

#if defined(__CUDA_ARCH_FEAT_SM103_ALL) || defined(__CUDA_ARCH_FEAT_SM100_ALL) || \
    defined(__CUDA_ARCH_FEAT_SM101_ALL) || defined(__CUDA_ARCH_SPECIFIC__) ||     \
    defined(__CUDA_ARCH_FAMILY_SPECIFIC__)
#define TC_OK 1
#else
#define TC_OK 0
#endif

// ================= f32x2 helpers =================
DEVFN unsigned long long pack2(float lo, float hi) {
    unsigned long long r;
    asm("mov.b64 %0, {%1,%2};" : "=l"(r) : "f"(lo), "f"(hi));
    return r;
}
DEVFN void unpack2(unsigned long long v, float& lo, float& hi) {
    asm("mov.b64 {%0,%1}, %2;" : "=f"(lo), "=f"(hi) : "l"(v));
}
DEVFN void fma2(unsigned long long& d, unsigned long long a, unsigned long long b) {
    asm("fma.rn.f32x2 %0, %1, %2, %0;" : "+l"(d) : "l"(a), "l"(b));
}
DEVFN float sigf(float x) { return __fdividef(1.f, 1.f + __expf(-x)); }
DEVFN float reluf(float x) { return fmaxf(x, 0.f); }

static constexpr int BATCH = 8192;
static constexpr int TT    = 30;
static constexpr int MBT   = BATCH * TT;   // 245760

// ================= scratch (static __device__, no allocation) =================
__device__ float g_bufA[(size_t)MBT * 512];
__device__ float g_bufB[(size_t)MBT * 256];
__device__ float g_h1[(size_t)BATCH * 256];
__device__ float g_xz[(size_t)2 * MBT * 1024];
__device__ __align__(128) float g_ru1[2 * 64 * 64 * 4];
__device__ __align__(128) float g_ru2[2 * 128 * 128 * 4];
__device__ __align__(128) float g_ru3[2 * 256 * 256 * 4];
__device__ __align__(128) __nv_bfloat16 g_w1h[2 * 256 * 128],  g_w1l[2 * 256 * 128];
__device__ __align__(128) __nv_bfloat16 g_w2h[2 * 512 * 128],  g_w2l[2 * 512 * 128];
__device__ __align__(128) __nv_bfloat16 g_w3h[2 * 1024 * 256], g_w3l[2 * 1024 * 256];
__device__ __align__(128) __nv_bfloat16 g_wdh[256 * 15360],    g_wdl[256 * 15360];
__device__ __align__(128) float g_wf1[2 * 128 * 256];     // float fallback weights
__device__ __align__(128) float g_wf2[2 * 128 * 512];
__device__ __align__(128) float g_wf3[2 * 256 * 1024];
__device__ float g_bg1[512], g_bg2[1024], g_bg3[2048];

// ================= tcgen05 helpers (guarded) =================
DEVFN unsigned smem_u32(const void* p) {
    unsigned a;
    asm("{ .reg .u64 t; cvta.to.shared.u64 t, %1; cvt.u32.u64 %0, t; }" : "=r"(a) : "l"(p));
    return a;
}
#if TC_OK
DEVFN unsigned elect1() {
    unsigned p;
    asm("{\n\t.reg .pred p;\n\telect.sync _|p, 0xFFFFFFFF;\n\tselp.b32 %0, 1, 0, p;\n\t}" : "=r"(p));
    return p;
}
#define SWZ(x) ((x) ^ (((x) >> 3) & 0x70))
static constexpr unsigned long long DESC_BASE =
    (2ull << 61) | (1ull << 46) | (64ull << 32) | (1ull << 16);
DEVFN unsigned long long mkdesc(unsigned a) { return DESC_BASE | ((a >> 4) & 0x3FFF); }
DEVFN void mma_f16_ss(unsigned d, unsigned long long ad, unsigned long long bd,
                      unsigned idesc, unsigned en) {
    asm volatile(
        "{\n\t.reg .pred p;\n\tsetp.ne.u32 p, %5, 0;\n\t"
        "tcgen05.mma.cta_group::1.kind::f16 [%0], %1, %2, %3, {%4, %4, %4, %4}, p;\n\t}"
        :: "r"(d), "l"(ad), "l"(bd), "r"(idesc), "r"(0u), "r"(en) : "memory");
}
#define TC_ALLOC(sm, n) \
    asm volatile("tcgen05.alloc.cta_group::1.sync.aligned.shared::cta.b32 [%0], %1;" :: "r"(sm), "r"(n) : "memory")
#define TC_RELQ() asm volatile("tcgen05.relinquish_alloc_permit.cta_group::1.sync.aligned;")
#define TC_DEALLOC(t, n) asm volatile("tcgen05.dealloc.cta_group::1.sync.aligned.b32 %0, %1;" :: "r"(t), "r"(n))
#define TC_COMMIT(mb) \
    asm volatile("tcgen05.commit.cta_group::1.mbarrier::arrive::one.shared::cluster.b64 [%0];" :: "r"(mb) : "memory")
#define TC_FENCE_AFTER() asm volatile("tcgen05.fence::after_thread_sync;" ::: "memory")
#define TC_WAIT_LD() asm volatile("tcgen05.wait::ld.sync.aligned;" ::: "memory")
#define FENCE_ASYNC() asm volatile("fence.proxy.async.shared::cta;" ::: "memory")
#define MBAR_INIT(mb, c) asm volatile("mbarrier.init.shared.b64 [%0], %1;" :: "r"(mb), "r"(c) : "memory")
DEVFN void mbar_wait(unsigned mb, unsigned parity) {
    asm volatile(
        "{\n\t.reg .pred P;\n\t"
        "W_%=:\n\t"
        "mbarrier.try_wait.parity.acquire.cta.shared::cta.b64 P, [%0], %1, 0x989680;\n\t"
        "@P bra.uni D_%=;\n\t"
        "bra.uni W_%=;\n\t"
        "D_%=:\n\t}"
        :: "r"(mb), "r"(parity) : "memory");
}
DEVFN void ldtm32(unsigned* r, unsigned a) {
    asm volatile(
        "tcgen05.ld.sync.aligned.32x32b.x32.b32 "
        "{%0,%1,%2,%3,%4,%5,%6,%7,%8,%9,%10,%11,%12,%13,%14,%15,"
        "%16,%17,%18,%19,%20,%21,%22,%23,%24,%25,%26,%27,%28,%29,%30,%31}, [%32];"
        : "=r"(r[0]), "=r"(r[1]), "=r"(r[2]), "=r"(r[3]), "=r"(r[4]), "=r"(r[5]),
          "=r"(r[6]), "=r"(r[7]), "=r"(r[8]), "=r"(r[9]), "=r"(r[10]), "=r"(r[11]),
          "=r"(r[12]), "=r"(r[13]), "=r"(r[14]), "=r"(r[15]), "=r"(r[16]), "=r"(r[17]),
          "=r"(r[18]), "=r"(r[19]), "=r"(r[20]), "=r"(r[21]), "=r"(r[22]), "=r"(r[23]),
          "=r"(r[24]), "=r"(r[25]), "=r"(r[26]), "=r"(r[27]), "=r"(r[28]), "=r"(r[29]),
          "=r"(r[30]), "=r"(r[31])
        : "r"(a));
}
#endif  // TC_OK

// ================= prep =================
DEVFN void bfsplit(float v, __nv_bfloat16& hi, __nv_bfloat16& lo) {
    hi = __float2bfloat16(v);
    lo = __float2bfloat16(v - __bfloat162float(hi));
}
DEVFN void upack1(long i, const float* Uf, const float* Ub, float* dst, int U) {
    long per = (long)U * U * 4;
    int d = i >= per; i -= (long)d * per;
    int g = (int)(i & 3); long r = i >> 2; int j = (int)(r % U); int k = (int)(r / U);
    dst[(size_t)d * per + i] = (d ? Ub : Uf)[(size_t)k * 4 * U + g * U + j];
}
DEVFN void wsplit1(long i, const float* Wf, const float* Wb, __nv_bfloat16* hi,
                   __nv_bfloat16* lo, int DIN, int U, int Kpad) {
    long per = (long)4 * U * Kpad;
    int d = i >= per; i -= (long)d * per;
    int kp = (int)(i % Kpad); long n = i / Kpad;
    int g = (int)(n & 3); int j = (int)(n >> 2);
    float v = (kp < DIN) ? (d ? Wb : Wf)[(size_t)kp * 4 * U + g * U + j] : 0.f;
    __nv_bfloat16 h, l; bfsplit(v, h, l);
    hi[(size_t)d * per + i] = h;
    lo[(size_t)d * per + i] = l;
}
DEVFN void wflt1(long i, const float* Wf, const float* Wb, float* dst, int DIN, int U,
                 int Kpad) {
    long per = (long)Kpad * 4 * U;
    int d = i >= per; i -= (long)d * per;
    int n = (int)(i % (4 * U)); long kp = i / (4 * U);
    int g = n & 3, j = n >> 2;
    float v = (kp < DIN) ? (d ? Wb : Wf)[(size_t)kp * 4 * U + g * U + j] : 0.f;
    dst[(size_t)d * per + i] = v;
}
DEVFN void bpack1(long i, const float* bf_, const float* bb_, float* dst, int U) {
    int N = 4 * U;
    int d = i >= N; i -= (long)d * N;
    int g = (int)(i & 3); int j = (int)(i >> 2);
    dst[(size_t)d * N + i] = (d ? bb_ : bf_)[g * U + j];
}

__global__ void prep_lstm(
    const float* u1f, const float* u1b, const float* u2f, const float* u2b,
    const float* u3f, const float* u3b,
    const float* w1f, const float* w1b, const float* w2f, const float* w2b,
    const float* w3f, const float* w3b,
    const float* b1f, const float* b1b, const float* b2f, const float* b2b,
    const float* b3f, const float* b3b) {
    constexpr long C0 = 2L * 64 * 64 * 4,   C1 = 2L * 128 * 128 * 4;
    constexpr long C2 = 2L * 256 * 256 * 4, C3 = 2L * 256 * 128;
    constexpr long C4 = 2L * 512 * 128,     C5 = 2L * 1024 * 256;
    constexpr long F1 = 2L * 128 * 256, F2 = 2L * 128 * 512, F3 = 2L * 256 * 1024;
    const long total = C0 + C1 + C2 + C3 + C4 + C5 + F1 + F2 + F3 + 2L * (256 + 512 + 1024);
    for (long idx = blockIdx.x * (long)blockDim.x + threadIdx.x; idx < total;
         idx += (long)gridDim.x * blockDim.x) {
        long i = idx;
        if (i < C0) { upack1(i, u1f, u1b, g_ru1, 64); continue; } i -= C0;
        if (i < C1) { upack1(i, u2f, u2b, g_ru2, 128); continue; } i -= C1;
        if (i < C2) { upack1(i, u3f, u3b, g_ru3, 256); continue; } i -= C2;
        if (i < C3) { wsplit1(i, w1f, w1b, g_w1h, g_w1l, 126, 64, 128); continue; } i -= C3;
        if (i < C4) { wsplit1(i, w2f, w2b, g_w2h, g_w2l, 128, 128, 128); continue; } i -= C4;
        if (i < C5) { wsplit1(i, w3f, w3b, g_w3h, g_w3l, 256, 256, 256); continue; } i -= C5;
        if (i < F1) { wflt1(i, w1f, w1b, g_wf1, 126, 64, 128); continue; } i -= F1;
        if (i < F2) { wflt1(i, w2f, w2b, g_wf2, 128, 128, 128); continue; } i -= F2;
        if (i < F3) { wflt1(i, w3f, w3b, g_wf3, 256, 256, 256); continue; } i -= F3;
        if (i < 512) { bpack1(i, b1f, b1b, g_bg1, 64); continue; } i -= 512;
        if (i < 1024) { bpack1(i, b2f, b2b, g_bg2, 128); continue; } i -= 1024;
        bpack1(i, b3f, b3b, g_bg3, 256);
    }
}

__global__ void prep_dense(const float* __restrict__ W) {
    const long total = 256L * 15360;
    for (long idx = blockIdx.x * (long)blockDim.x + threadIdx.x; idx < total;
         idx += (long)gridDim.x * blockDim.x) {
        int n = (int)(idx / 15360), k = (int)(idx % 15360);
        __nv_bfloat16 h, l; bfsplit(W[(size_t)k * 256 + n], h, l);
        g_wdh[idx] = h;
        g_wdl[idx] = l;
    }
}

// ================= GEMM: C[z] = A @ W[z] + bias[z] (opt relu) ==================
static constexpr int SM_TMEM = 1024;
static constexpr int SM_MBAR = 1040;
static constexpr int SM_AHI  = 2048;
static constexpr int SM_ALO  = 34816;
static constexpr int SM_WHI  = 67584;
static constexpr int SM_WLO  = 133120;
static constexpr int SMEMG   = 198656;
static constexpr unsigned GEMM_IDESC =
    (1u << 4) | (1u << 7) | (1u << 10) | ((256u / 8) << 17) | (8u << 24);

template <bool RELU>
__global__ void __launch_bounds__(256) gemm_kernel(
    const float* __restrict__ A, const __nv_bfloat16* __restrict__ Whi,
    const __nv_bfloat16* __restrict__ Wlo, const float* __restrict__ Wflt,
    const float* __restrict__ bias, float* __restrict__ C,
    int K, int Kpad, int Ndir, size_t strideCz) {
    extern __shared__ char smem[];
    const int tid = threadIdx.x, wid = tid >> 5, lane = tid & 31;
    const int m0 = blockIdx.x * 128, n0 = blockIdx.y * 256, z = blockIdx.z;

    reinterpret_cast<float*>(smem)[tid] = bias[(size_t)z * Ndir + n0 + tid];

#if TC_OK
    const unsigned sb = smem_u32(smem);
    if (tid == 0) { MBAR_INIT(sb + SM_MBAR, 1); MBAR_INIT(sb + SM_MBAR + 8, 1); }
    if (wid == 0) { TC_ALLOC(sb + SM_TMEM, 256); TC_RELQ(); }
    __syncthreads();
    unsigned tmem;
    asm volatile("ld.shared.b32 %0, [%1];" : "=r"(tmem) : "r"(sb + SM_TMEM));

    const float* Ag = A + (size_t)m0 * K;
    const __nv_bfloat16* WhG = Whi + ((size_t)z * Ndir + n0) * Kpad;
    const __nv_bfloat16* WlG = Wlo + ((size_t)z * Ndir + n0) * Kpad;

    const int KT = Kpad / 64;
    int ph0 = 0, ph1 = 0;
    for (int kt = 0; kt < KT; ++kt) {
        const int b = kt & 1;
        if (kt >= 2) {
            if (b == 0) { mbar_wait(sb + SM_MBAR, ph0); ph0 ^= 1; }
            else        { mbar_wait(sb + SM_MBAR + 8, ph1); ph1 ^= 1; }
        }
        char* aHi = smem + SM_AHI + b * 16384;
        char* aLo = smem + SM_ALO + b * 16384;
        char* wHi = smem + SM_WHI + b * 32768;
        char* wLo = smem + SM_WLO + b * 32768;
        if ((K & 3) == 0) {
            for (int i = tid; i < 2048; i += 256) {
                int row = i >> 4, c4 = (i & 15) * 4;
                int kg = kt * 64 + c4;
                float4 v = make_float4(0.f, 0.f, 0.f, 0.f);
                if (kg < K) v = *reinterpret_cast<const float4*>(Ag + (size_t)row * K + kg);
                __nv_bfloat16 h0 = __float2bfloat16(v.x), h1 = __float2bfloat16(v.y);
                __nv_bfloat16 h2 = __float2bfloat16(v.z), h3 = __float2bfloat16(v.w);
                unsigned hiA = ((unsigned)__bfloat16_as_ushort(h1) << 16) | __bfloat16_as_ushort(h0);
                unsigned hiB = ((unsigned)__bfloat16_as_ushort(h3) << 16) | __bfloat16_as_ushort(h2);
                __nv_bfloat16 l0 = __float2bfloat16(v.x - __bfloat162float(h0));
                __nv_bfloat16 l1 = __float2bfloat16(v.y - __bfloat162float(h1));
                __nv_bfloat16 l2 = __float2bfloat16(v.z - __bfloat162float(h2));
                __nv_bfloat16 l3 = __float2bfloat16(v.w - __bfloat162float(h3));
                unsigned loA = ((unsigned)__bfloat16_as_ushort(l1) << 16) | __bfloat16_as_ushort(l0);
                unsigned loB = ((unsigned)__bfloat16_as_ushort(l3) << 16) | __bfloat16_as_ushort(l2);
                unsigned off = SWZ(row * 128 + c4 * 2);
                *reinterpret_cast<unsigned long long*>(aHi + off) =
                    ((unsigned long long)hiB << 32) | hiA;
                *reinterpret_cast<unsigned long long*>(aLo + off) =
                    ((unsigned long long)loB << 32) | loA;
            }
        } else {
            for (int i = tid; i < 8192; i += 256) {
                int row = i >> 6, c = i & 63;
                int kg = kt * 64 + c;
                float v = (kg < K) ? Ag[(size_t)row * K + kg] : 0.f;
                __nv_bfloat16 h, l; bfsplit(v, h, l);
                unsigned off = SWZ(row * 128 + c * 2);
                *reinterpret_cast<__nv_bfloat16*>(aHi + off) = h;
                *reinterpret_cast<__nv_bfloat16*>(aLo + off) = l;
            }
        }
        for (int i = tid; i < 2048; i += 256) {
            int n = i >> 3, c16 = i & 7;
            unsigned off = SWZ(n * 128 + c16 * 16);
            *reinterpret_cast<uint4*>(wHi + off) =
                *reinterpret_cast<const uint4*>(WhG + (size_t)n * Kpad + kt * 64 + c16 * 8);
            *reinterpret_cast<uint4*>(wLo + off) =
                *reinterpret_cast<const uint4*>(WlG + (size_t)n * Kpad + kt * 64 + c16 * 8);
        }
        FENCE_ASYNC();
        __syncthreads();
        if (wid == 0 && elect1()) {
            unsigned aH = sb + SM_AHI + b * 16384, aL = sb + SM_ALO + b * 16384;
            unsigned wH = sb + SM_WHI + b * 32768, wL = sb + SM_WLO + b * 32768;
            unsigned long long ads[3] = {mkdesc(aH), mkdesc(aL), mkdesc(aH)};
            unsigned long long bds[3] = {mkdesc(wH), mkdesc(wH), mkdesc(wL)};
#pragma unroll
            for (int s = 0; s < 3; ++s)
#pragma unroll
                for (int ks = 0; ks < 4; ++ks)
                    mma_f16_ss(tmem, ads[s] + ks * 2, bds[s] + ks * 2, GEMM_IDESC,
                               !(kt == 0 && s == 0 && ks == 0));
            TC_COMMIT(sb + SM_MBAR + b * 8);
        }
    }
    {
        const int bl = (KT - 1) & 1;
        mbar_wait(sb + SM_MBAR + bl * 8, bl ? ph1 : ph0);
    }
    TC_FENCE_AFTER();
    {
        const int row = (wid & 3) * 32 + lane;
        const int cb0 = (wid >> 2) * 128;
        const float* bs = reinterpret_cast<const float*>(smem);
        float* Crow = C + (size_t)z * strideCz + (size_t)(m0 + row) * Ndir + n0;
#pragma unroll
        for (int ch = 0; ch < 4; ++ch) {
            unsigned r[32];
            ldtm32(r, tmem + cb0 + ch * 32);
            TC_WAIT_LD();
            int cb = cb0 + ch * 32;
#pragma unroll
            for (int q = 0; q < 8; ++q) {
                float4 v;
                v.x = __uint_as_float(r[q * 4 + 0]) + bs[cb + q * 4 + 0];
                v.y = __uint_as_float(r[q * 4 + 1]) + bs[cb + q * 4 + 1];
                v.z = __uint_as_float(r[q * 4 + 2]) + bs[cb + q * 4 + 2];
                v.w = __uint_as_float(r[q * 4 + 3]) + bs[cb + q * 4 + 3];
                if (RELU) { v.x = reluf(v.x); v.y = reluf(v.y); v.z = reluf(v.z); v.w = reluf(v.w); }
                *reinterpret_cast<float4*>(Crow + cb + q * 4) = v;
            }
        }
    }
    __syncthreads();
    if (wid == 0) TC_DEALLOC(tmem, 256);
#else
    // ---------- scalar f32x2 fallback ----------
    (void)Whi; (void)Wlo;
    float* a_s = reinterpret_cast<float*>(smem + 2048);   // [32][66]
    const float* bs = reinterpret_cast<const float*>(smem);
    const float* Wz = Wflt + (size_t)z * Kpad * Ndir;
    const int ng = wid & 1, rg = wid >> 1;
    const int nl = ng * 128 + lane * 4;
    const int rb = rg * 16;
    for (int hh = 0; hh < 2; ++hh) {
        const int r0 = m0 + hh * 64;
        unsigned long long acc[8][4];
#pragma unroll
        for (int p = 0; p < 8; p++)
#pragma unroll
            for (int c = 0; c < 4; c++) acc[p][c] = 0ull;
        for (int kt = 0; kt < Kpad; kt += 32) {
            __syncthreads();
            for (int i = tid; i < 64 * 32; i += 256) {
                int r = i >> 5, k = i & 31;
                int kg = kt + k;
                a_s[k * 66 + r] = (kg < K) ? A[(size_t)(r0 + r) * K + kg] : 0.f;
            }
            __syncthreads();
#pragma unroll 2
            for (int k = 0; k < 32; k++) {
                float4 w = *reinterpret_cast<const float4*>(
                    &Wz[(size_t)(kt + k) * Ndir + n0 + nl]);
                unsigned long long w0 = pack2(w.x, w.x), w1 = pack2(w.y, w.y);
                unsigned long long w2 = pack2(w.z, w.z), w3 = pack2(w.w, w.w);
#pragma unroll
                for (int p = 0; p < 8; p++) {
                    unsigned long long a2 =
                        *reinterpret_cast<const unsigned long long*>(&a_s[k * 66 + rb + 2 * p]);
                    fma2(acc[p][0], a2, w0);
                    fma2(acc[p][1], a2, w1);
                    fma2(acc[p][2], a2, w2);
                    fma2(acc[p][3], a2, w3);
                }
            }
        }
#pragma unroll
        for (int p = 0; p < 8; p++) {
            float lo[4], hi[4];
#pragma unroll
            for (int c = 0; c < 4; c++) unpack2(acc[p][c], lo[c], hi[c]);
            int r = r0 + rb + 2 * p;
            float4 v0 = {lo[0] + bs[nl], lo[1] + bs[nl + 1], lo[2] + bs[nl + 2], lo[3] + bs[nl + 3]};
            float4 v1 = {hi[0] + bs[nl], hi[1] + bs[nl + 1], hi[2] + bs[nl + 2], hi[3] + bs[nl + 3]};
            if (RELU) {
                v0.x = reluf(v0.x); v0.y = reluf(v0.y); v0.z = reluf(v0.z); v0.w = reluf(v0.w);
                v1.x = reluf(v1.x); v1.y = reluf(v1.y); v1.z = reluf(v1.z); v1.w = reluf(v1.w);
            }
            float* Cr = C + (size_t)z * strideCz + (size_t)r * Ndir + n0 + nl;
            *reinterpret_cast<float4*>(Cr) = v0;
            *reinterpret_cast<float4*>(Cr + Ndir) = v1;
        }
    }
#endif
}

// ================= recurrent BiLSTM (f32x2, K = U) =================
template <int U, int THREADS, int ROWS, int RPW>
__global__ void __launch_bounds__(THREADS, 2) lstm_rec(
    const float* __restrict__ xz,   // [2][MBT][4U], n = j*4+g
    const float* __restrict__ Upk,  // [2][(k*U+j)*4+g]
    float* __restrict__ out) {      // [MBT][2U]
    constexpr int RP    = ROWS + 2;
    constexpr int NCH   = U / 32, NW = THREADS / 32;
    constexpr int PAIRS = RPW / 2;
    constexpr int RG    = ROWS / RPW, CHG = NW / RG, CPW = NCH / CHG;
    static_assert(CHG * RG == NW && CPW * CHG == NCH, "mapping");

    extern __shared__ float h_s[];   // [2][U][RP]
    const int tid = threadIdx.x, lane = tid & 31, warp = tid >> 5;
    const int dir = blockIdx.y, b0 = blockIdx.x * ROWS;
    const int chg = warp % CHG, rb = (warp / CHG) * RPW;
    const float* Ud  = Upk + (size_t)dir * U * 4 * U;
    const float* xzd = xz + (size_t)dir * MBT * 4 * U;

    unsigned long long c2[CPW][PAIRS];
#pragma unroll
    for (int cg = 0; cg < CPW; ++cg)
#pragma unroll
        for (int p = 0; p < PAIRS; ++p) c2[cg][p] = 0ull;

    for (int i = tid; i < 2 * U * RP; i += THREADS) h_s[i] = 0.f;

    int cur = 0;
    for (int step = 0; step < TT; ++step) {
        const int t = dir ? (TT - 1 - step) : step;
        __syncthreads();
        float*       hn = h_s + (cur ^ 1) * U * RP;
        const float* hc = h_s + cur * U * RP;
#pragma unroll 1
        for (int cg = 0; cg < CPW; ++cg) {
            const int j = (chg * CPW + cg) * 32 + lane;
            unsigned long long ai[PAIRS], af[PAIRS], ag[PAIRS], ao[PAIRS];
#pragma unroll
            for (int p = 0; p < PAIRS; ++p) {
                size_t m = (size_t)(b0 + rb + 2 * p) * TT + t;
                float4 x0 = *reinterpret_cast<const float4*>(xzd + m * 4 * U + j * 4);
                float4 x1 = *reinterpret_cast<const float4*>(xzd + (m + TT) * 4 * U + j * 4);
                ai[p] = pack2(x0.x, x1.x); af[p] = pack2(x0.y, x1.y);
                ag[p] = pack2(x0.z, x1.z); ao[p] = pack2(x0.w, x1.w);
            }
            const float* wrow = Ud + (size_t)j * 4;
#pragma unroll 2
            for (int k = 0; k < U; ++k) {
                float4 u = *reinterpret_cast<const float4*>(wrow);
                wrow += 4 * U;
                unsigned long long wi = pack2(u.x, u.x), wf = pack2(u.y, u.y);
                unsigned long long wg = pack2(u.z, u.z), wo = pack2(u.w, u.w);
                const float* src = &hc[k * RP + rb];
#pragma unroll
                for (int p = 0; p < PAIRS; ++p) {
                    unsigned long long a2 =
                        *reinterpret_cast<const unsigned long long*>(src + 2 * p);
                    fma2(ai[p], a2, wi); fma2(af[p], a2, wf);
                    fma2(ag[p], a2, wg); fma2(ao[p], a2, wo);
                }
            }
#pragma unroll
            for (int p = 0; p < PAIRS; ++p) {
                float i0, i1, f0, f1, gg0, gg1, o0, o1, co0, co1;
                unpack2(ai[p], i0, i1); unpack2(af[p], f0, f1);
                unpack2(ag[p], gg0, gg1); unpack2(ao[p], o0, o1);
                unpack2(c2[cg][p], co0, co1);
                float cn0 = sigf(f0) * co0 + sigf(i0) * reluf(gg0);
                float cn1 = sigf(f1) * co1 + sigf(i1) * reluf(gg1);
                float h0  = sigf(o0) * reluf(cn0);
                float h1  = sigf(o1) * reluf(cn1);
                c2[cg][p] = pack2(cn0, cn1);
                int r0 = rb + 2 * p;
                *reinterpret_cast<unsigned long long*>(&hn[j * RP + r0]) = pack2(h0, h1);
                size_t ob = ((size_t)(b0 + r0) * TT + t) * (2 * U) + (size_t)dir * U + j;
                out[ob]                      = h0;
                out[ob + (size_t)TT * 2 * U] = h1;
            }
        }
        cur ^= 1;
    }
}

// ================= tail =================
__global__ void __launch_bounds__(128) tail_kernel(
    const float* __restrict__ H1,
    const float* __restrict__ W2, const float* __restrict__ B2,
    const float* __restrict__ W3, const float* __restrict__ B3,
    const float* __restrict__ G, const float* __restrict__ Bb,
    const float* __restrict__ M, const float* __restrict__ V,
    const float* __restrict__ WO, const float* __restrict__ BO,
    float* __restrict__ Out) {
    __shared__ float h1s[4][256];
    __shared__ float h2s[4][128];
    __shared__ float h3s[4][64];
    int tid = threadIdx.x, lane = tid & 31, w = tid >> 5;
    int r0 = blockIdx.x * 4;
    for (int i = tid; i < 4 * 256; i += 128) h1s[i >> 8][i & 255] = H1[(size_t)r0 * 256 + i];
    __syncthreads();
    {
        int j = lane * 4;
        float4 bv = *reinterpret_cast<const float4*>(&B2[j]);
        float a0 = bv.x, a1 = bv.y, a2 = bv.z, a3 = bv.w;
#pragma unroll 4
        for (int k = 0; k < 256; k++) {
            float a = h1s[w][k];
            float4 wv = *reinterpret_cast<const float4*>(&W2[(size_t)k * 128 + j]);
            a0 += a * wv.x; a1 += a * wv.y; a2 += a * wv.z; a3 += a * wv.w;
        }
        h2s[w][j] = reluf(a0); h2s[w][j + 1] = reluf(a1);
        h2s[w][j + 2] = reluf(a2); h2s[w][j + 3] = reluf(a3);
    }
    __syncwarp();
    {
        int j = lane * 2;
        float a0 = B3[j], a1 = B3[j + 1];
#pragma unroll 4
        for (int k = 0; k < 128; k++) {
            float a = h2s[w][k];
            float2 wv = *reinterpret_cast<const float2*>(&W3[(size_t)k * 64 + j]);
            a0 += a * wv.x; a1 += a * wv.y;
        }
        a0 = reluf(a0); a1 = reluf(a1);
        float s0 = rsqrtf(V[j] + 1e-3f) * G[j];
        float s1 = rsqrtf(V[j + 1] + 1e-3f) * G[j + 1];
        h3s[w][j]     = (a0 - M[j]) * s0 + Bb[j];
        h3s[w][j + 1] = (a1 - M[j + 1]) * s1 + Bb[j + 1];
    }
    __syncwarp();
    float logit = -3.0e38f;
    if (lane < 26) {
        float a = BO[lane];
#pragma unroll 4
        for (int k = 0; k < 64; k++) a += h3s[w][k] * WO[(size_t)k * 26 + lane];
        logit = a;
    }
    float mx = logit;
#pragma unroll
    for (int o = 16; o; o >>= 1) mx = fmaxf(mx, __shfl_xor_sync(0xffffffffu, mx, o));
    float e = (lane < 26) ? __expf(logit - mx) : 0.f;
    float s = e;
#pragma unroll
    for (int o = 16; o; o >>= 1) s += __shfl_xor_sync(0xffffffffu, s, o);
    if (lane < 26) Out[(size_t)(r0 + w) * 26 + lane] = e * __fdividef(1.f, s);
}

// ================= launch =================
extern "C" void kernel_launch(void* const* d_in, const int* in_sizes, int n_in,
                              void* d_out, int out_size) {
    const float* x   = (const float*)d_in[0];
    const float* w1f = (const float*)d_in[1];
    const float* u1f = (const float*)d_in[2];
    const float* b1f = (const float*)d_in[3];
    const float* w1b = (const float*)d_in[4];
    const float* u1b = (const float*)d_in[5];
    const float* b1b = (const float*)d_in[6];
    const float* w2f = (const float*)d_in[7];
    const float* u2f = (const float*)d_in[8];
    const float* b2f = (const float*)d_in[9];
    const float* w2b = (const float*)d_in[10];
    const float* u2b = (const float*)d_in[11];
    const float* b2b = (const float*)d_in[12];
    const float* w3f = (const float*)d_in[13];
    const float* u3f = (const float*)d_in[14];
    const float* b3f = (const float*)d_in[15];
    const float* w3b = (const float*)d_in[16];
    const float* u3b = (const float*)d_in[17];
    const float* b3b = (const float*)d_in[18];
    const float* d1w = (const float*)d_in[19];
    const float* d1b = (const float*)d_in[20];
    const float* d2w = (const float*)d_in[21];
    const float* d2b = (const float*)d_in[22];
    const float* d3w = (const float*)d_in[23];
    const float* d3b = (const float*)d_in[24];
    const float* bng = (const float*)d_in[25];
    const float* bnb = (const float*)d_in[26];
    const float* bnm = (const float*)d_in[27];
    const float* bnv = (const float*)d_in[28];
    const float* ow  = (const float*)d_in[29];
    const float* ob  = (const float*)d_in[30];

    float *bufA, *bufB, *h1, *xz, *ru1, *ru2, *ru3, *bg1, *bg2, *bg3;
    float *wf1, *wf2, *wf3;
    __nv_bfloat16 *w1h, *w1l, *w2h, *w2l, *w3h, *w3l, *wdh, *wdl;
    cudaGetSymbolAddress((void**)&bufA, g_bufA);
    cudaGetSymbolAddress((void**)&bufB, g_bufB);
    cudaGetSymbolAddress((void**)&h1, g_h1);
    cudaGetSymbolAddress((void**)&xz, g_xz);
    cudaGetSymbolAddress((void**)&ru1, g_ru1);
    cudaGetSymbolAddress((void**)&ru2, g_ru2);
    cudaGetSymbolAddress((void**)&ru3, g_ru3);
    cudaGetSymbolAddress((void**)&bg1, g_bg1);
    cudaGetSymbolAddress((void**)&bg2, g_bg2);
    cudaGetSymbolAddress((void**)&bg3, g_bg3);
    cudaGetSymbolAddress((void**)&wf1, g_wf1);
    cudaGetSymbolAddress((void**)&wf2, g_wf2);
    cudaGetSymbolAddress((void**)&wf3, g_wf3);
    cudaGetSymbolAddress((void**)&w1h, g_w1h);
    cudaGetSymbolAddress((void**)&w1l, g_w1l);
    cudaGetSymbolAddress((void**)&w2h, g_w2h);
    cudaGetSymbolAddress((void**)&w2l, g_w2l);
    cudaGetSymbolAddress((void**)&w3h, g_w3h);
    cudaGetSymbolAddress((void**)&w3l, g_w3l);
    cudaGetSymbolAddress((void**)&wdh, g_wdh);
    cudaGetSymbolAddress((void**)&wdl, g_wdl);

    cudaFuncSetAttribute(gemm_kernel<false>, cudaFuncAttributeMaxDynamicSharedMemorySize, SMEMG);
    cudaFuncSetAttribute(gemm_kernel<true>,  cudaFuncAttributeMaxDynamicSharedMemorySize, SMEMG);
    const int s1 = 2 * 64 * 66 * 4, s2 = 2 * 128 * 66 * 4, s3 = 2 * 256 * 34 * 4;
    cudaFuncSetAttribute((lstm_rec<64, 256, 64, 16>),  cudaFuncAttributeMaxDynamicSharedMemorySize, s1);
    cudaFuncSetAttribute((lstm_rec<128, 256, 64, 16>), cudaFuncAttributeMaxDynamicSharedMemorySize, s2);
    cudaFuncSetAttribute((lstm_rec<256, 256, 32, 16>), cudaFuncAttributeMaxDynamicSharedMemorySize, s3);

    prep_lstm<<<512, 256>>>(u1f, u1b, u2f, u2b, u3f, u3b,
                            w1f, w1b, w2f, w2b, w3f, w3b,
                            b1f, b1b, b2f, b2b, b3f, b3b);
    prep_dense<<<512, 256>>>(d1w);

    // L1
    gemm_kernel<false><<<dim3(MBT / 128, 1, 2), 256, SMEMG>>>(
        x, w1h, w1l, wf1, bg1, xz, 126, 128, 256, (size_t)MBT * 256);
    lstm_rec<64, 256, 64, 16><<<dim3(BATCH / 64, 2), 256, s1>>>(xz, ru1, bufA);
    // L2
    gemm_kernel<false><<<dim3(MBT / 128, 2, 2), 256, SMEMG>>>(
        bufA, w2h, w2l, wf2, bg2, xz, 128, 128, 512, (size_t)MBT * 512);
    lstm_rec<128, 256, 64, 16><<<dim3(BATCH / 64, 2), 256, s2>>>(xz, ru2, bufB);
    // L3
    gemm_kernel<false><<<dim3(MBT / 128, 4, 2), 256, SMEMG>>>(
        bufB, w3h, w3l, wf3, bg3, xz, 256, 256, 1024, (size_t)MBT * 1024);
    lstm_rec<256, 256, 32, 16><<<dim3(BATCH / 32, 2), 256, s3>>>(xz, ru3, bufA);
    // dense1 (M=8192, K=15360, N=256) + relu; float fallback reads d1w natural layout
    gemm_kernel<true><<<dim3(BATCH / 128, 1, 1), 256, SMEMG>>>(
        bufA, wdh, wdl, d1w, d1b, h1, 15360, 15360, 256, 0);
    // tail
    tail_kernel<<<BATCH / 4, 128>>>(h1, d2w, d2b, d3w, d3b, bng, bnb, bnm, bnv, ow, ob,
                                    (float*)d_out);
    (void)in_sizes; (void)n_in; (void)out_size;
}

// round 11
// speedup vs baseline: 1.2105x; 1.2105x over previous
#include <cuda_runtime.h>
#include <cuda_bf16.h>
#include <cstdint>

#define DEVFN __device__ __forceinline__

#if defined(__CUDA_ARCH_FEAT_SM103_ALL) || defined(__CUDA_ARCH_FEAT_SM100_ALL) || \
    defined(__CUDA_ARCH_FEAT_SM101_ALL) || defined(__CUDA_ARCH_SPECIFIC__) ||     \
    defined(__CUDA_ARCH_FAMILY_SPECIFIC__)
#define TC_OK 1
#else
#define TC_OK 0
#endif

DEVFN float sigf(float x) { return __fdividef(1.f, 1.f + __expf(-x)); }
DEVFN float reluf(float x) { return fmaxf(x, 0.f); }

static constexpr int BATCH = 8192;
static constexpr int TT    = 30;
static constexpr int MBT   = BATCH * TT;   // 245760

// ================= scratch (static __device__, no allocation) =================
__device__ float g_bufA[(size_t)MBT * 512];
__device__ float g_bufB[(size_t)MBT * 256];
__device__ float g_h1[(size_t)BATCH * 256];
__device__ float g_xz[(size_t)2 * MBT * 1024];
__device__ float g_c[(size_t)2 * BATCH * 256];
__device__ __align__(128) __nv_bfloat16 g_uh1[2 * 256 * 64],   g_ul1[2 * 256 * 64];
__device__ __align__(128) __nv_bfloat16 g_uh2[2 * 512 * 128],  g_ul2[2 * 512 * 128];
__device__ __align__(128) __nv_bfloat16 g_uh3[2 * 1024 * 256], g_ul3[2 * 1024 * 256];
__device__ __align__(128) __nv_bfloat16 g_w1h[2 * 256 * 128],  g_w1l[2 * 256 * 128];
__device__ __align__(128) __nv_bfloat16 g_w2h[2 * 512 * 128],  g_w2l[2 * 512 * 128];
__device__ __align__(128) __nv_bfloat16 g_w3h[2 * 1024 * 256], g_w3l[2 * 1024 * 256];
__device__ __align__(128) __nv_bfloat16 g_wdh[256 * 15360],    g_wdl[256 * 15360];
__device__ float g_bg1[512], g_bg2[1024], g_bg3[2048];

// ================= tcgen05 helpers (guarded) =================
DEVFN unsigned smem_u32(const void* p) {
    unsigned a;
    asm("{ .reg .u64 t; cvta.to.shared.u64 t, %1; cvt.u32.u64 %0, t; }" : "=r"(a) : "l"(p));
    return a;
}
#if TC_OK
DEVFN unsigned elect1() {
    unsigned p;
    asm("{\n\t.reg .pred p;\n\telect.sync _|p, 0xFFFFFFFF;\n\tselp.b32 %0, 1, 0, p;\n\t}" : "=r"(p));
    return p;
}
#define SWZ(x) ((x) ^ (((x) >> 3) & 0x70))
static constexpr unsigned long long DESC_BASE =
    (2ull << 61) | (1ull << 46) | (64ull << 32) | (1ull << 16);
DEVFN unsigned long long mkdesc(unsigned a) { return DESC_BASE | ((a >> 4) & 0x3FFF); }
DEVFN void mma_f16_ss(unsigned d, unsigned long long ad, unsigned long long bd,
                      unsigned idesc, unsigned en) {
    asm volatile(
        "{\n\t.reg .pred p;\n\tsetp.ne.u32 p, %5, 0;\n\t"
        "tcgen05.mma.cta_group::1.kind::f16 [%0], %1, %2, %3, {%4, %4, %4, %4}, p;\n\t}"
        :: "r"(d), "l"(ad), "l"(bd), "r"(idesc), "r"(0u), "r"(en) : "memory");
}
#define TC_ALLOC(sm, n) \
    asm volatile("tcgen05.alloc.cta_group::1.sync.aligned.shared::cta.b32 [%0], %1;" :: "r"(sm), "r"(n) : "memory")
#define TC_RELQ() asm volatile("tcgen05.relinquish_alloc_permit.cta_group::1.sync.aligned;")
#define TC_DEALLOC(t, n) asm volatile("tcgen05.dealloc.cta_group::1.sync.aligned.b32 %0, %1;" :: "r"(t), "r"(n))
#define TC_COMMIT(mb) \
    asm volatile("tcgen05.commit.cta_group::1.mbarrier::arrive::one.shared::cluster.b64 [%0];" :: "r"(mb) : "memory")
#define TC_FENCE_AFTER() asm volatile("tcgen05.fence::after_thread_sync;" ::: "memory")
#define TC_FENCE_BEFORE() asm volatile("tcgen05.fence::before_thread_sync;" ::: "memory")
#define TC_WAIT_LD() asm volatile("tcgen05.wait::ld.sync.aligned;" ::: "memory")
#define FENCE_ASYNC() asm volatile("fence.proxy.async.shared::cta;" ::: "memory")
#define MBAR_INIT(mb, c) asm volatile("mbarrier.init.shared.b64 [%0], %1;" :: "r"(mb), "r"(c) : "memory")
DEVFN void mbar_wait(unsigned mb, unsigned parity) {
    asm volatile(
        "{\n\t.reg .pred P;\n\t"
        "W_%=:\n\t"
        "mbarrier.try_wait.parity.acquire.cta.shared::cta.b64 P, [%0], %1, 0x989680;\n\t"
        "@P bra.uni D_%=;\n\t"
        "bra.uni W_%=;\n\t"
        "D_%=:\n\t}"
        :: "r"(mb), "r"(parity) : "memory");
}
DEVFN void ldtm32(unsigned* r, unsigned a) {
    asm volatile(
        "tcgen05.ld.sync.aligned.32x32b.x32.b32 "
        "{%0,%1,%2,%3,%4,%5,%6,%7,%8,%9,%10,%11,%12,%13,%14,%15,"
        "%16,%17,%18,%19,%20,%21,%22,%23,%24,%25,%26,%27,%28,%29,%30,%31}, [%32];"
        : "=r"(r[0]), "=r"(r[1]), "=r"(r[2]), "=r"(r[3]), "=r"(r[4]), "=r"(r[5]),
          "=r"(r[6]), "=r"(r[7]), "=r"(r[8]), "=r"(r[9]), "=r"(r[10]), "=r"(r[11]),
          "=r"(r[12]), "=r"(r[13]), "=r"(r[14]), "=r"(r[15]), "=r"(r[16]), "=r"(r[17]),
          "=r"(r[18]), "=r"(r[19]), "=r"(r[20]), "=r"(r[21]), "=r"(r[22]), "=r"(r[23]),
          "=r"(r[24]), "=r"(r[25]), "=r"(r[26]), "=r"(r[27]), "=r"(r[28]), "=r"(r[29]),
          "=r"(r[30]), "=r"(r[31])
        : "r"(a));
}
#endif  // TC_OK

// ================= prep =================
DEVFN void bfsplit(float v, __nv_bfloat16& hi, __nv_bfloat16& lo) {
    hi = __float2bfloat16(v);
    lo = __float2bfloat16(v - __bfloat162float(hi));
}
// recurrent U for tcgen05 B: dst[d][n][k] = U[k][g*U+j], n = j*4+g
DEVFN void utc1(long i, const float* Uf, const float* Ub, __nv_bfloat16* hi,
                __nv_bfloat16* lo, int U) {
    long per = (long)4 * U * U;
    int d = i >= per; i -= (long)d * per;
    int k = (int)(i % U); long n = i / U;
    int g = (int)(n & 3); int j = (int)(n >> 2);
    float v = (d ? Ub : Uf)[(size_t)k * 4 * U + g * U + j];
    __nv_bfloat16 h, l; bfsplit(v, h, l);
    hi[(size_t)d * per + i] = h;
    lo[(size_t)d * per + i] = l;
}
DEVFN void wsplit1(long i, const float* Wf, const float* Wb, __nv_bfloat16* hi,
                   __nv_bfloat16* lo, int DIN, int U, int Kpad) {
    long per = (long)4 * U * Kpad;
    int d = i >= per; i -= (long)d * per;
    int kp = (int)(i % Kpad); long n = i / Kpad;
    int g = (int)(n & 3); int j = (int)(n >> 2);
    float v = (kp < DIN) ? (d ? Wb : Wf)[(size_t)kp * 4 * U + g * U + j] : 0.f;
    __nv_bfloat16 h, l; bfsplit(v, h, l);
    hi[(size_t)d * per + i] = h;
    lo[(size_t)d * per + i] = l;
}
DEVFN void bpack1(long i, const float* bf_, const float* bb_, float* dst, int U) {
    int N = 4 * U;
    int d = i >= N; i -= (long)d * N;
    int g = (int)(i & 3); int j = (int)(i >> 2);
    dst[(size_t)d * N + i] = (d ? bb_ : bf_)[g * U + j];
}

__global__ void prep_lstm(
    const float* u1f, const float* u1b, const float* u2f, const float* u2b,
    const float* u3f, const float* u3b,
    const float* w1f, const float* w1b, const float* w2f, const float* w2b,
    const float* w3f, const float* w3b,
    const float* b1f, const float* b1b, const float* b2f, const float* b2b,
    const float* b3f, const float* b3b) {
    constexpr long G1 = 2L * 256 * 64, G2 = 2L * 512 * 128, G3 = 2L * 1024 * 256;
    constexpr long C3 = 2L * 256 * 128, C4 = 2L * 512 * 128, C5 = 2L * 1024 * 256;
    const long total = G1 + G2 + G3 + C3 + C4 + C5 + 2L * (256 + 512 + 1024);
    for (long idx = blockIdx.x * (long)blockDim.x + threadIdx.x; idx < total;
         idx += (long)gridDim.x * blockDim.x) {
        long i = idx;
        if (i < G1) { utc1(i, u1f, u1b, g_uh1, g_ul1, 64); continue; } i -= G1;
        if (i < G2) { utc1(i, u2f, u2b, g_uh2, g_ul2, 128); continue; } i -= G2;
        if (i < G3) { utc1(i, u3f, u3b, g_uh3, g_ul3, 256); continue; } i -= G3;
        if (i < C3) { wsplit1(i, w1f, w1b, g_w1h, g_w1l, 126, 64, 128); continue; } i -= C3;
        if (i < C4) { wsplit1(i, w2f, w2b, g_w2h, g_w2l, 128, 128, 128); continue; } i -= C4;
        if (i < C5) { wsplit1(i, w3f, w3b, g_w3h, g_w3l, 256, 256, 256); continue; } i -= C5;
        if (i < 512) { bpack1(i, b1f, b1b, g_bg1, 64); continue; } i -= 512;
        if (i < 1024) { bpack1(i, b2f, b2b, g_bg2, 128); continue; } i -= 1024;
        bpack1(i, b3f, b3b, g_bg3, 256);
    }
}

__global__ void prep_dense(const float* __restrict__ W) {
    const long total = 256L * 15360;
    for (long idx = blockIdx.x * (long)blockDim.x + threadIdx.x; idx < total;
         idx += (long)gridDim.x * blockDim.x) {
        int n = (int)(idx / 15360), k = (int)(idx % 15360);
        __nv_bfloat16 h, l; bfsplit(W[(size_t)k * 256 + n], h, l);
        g_wdh[idx] = h;
        g_wdl[idx] = l;
    }
}

// ================= GEMM: C[z] = A @ W[z] + bias[z] (opt relu) ==================
static constexpr int SM_TMEM = 1024;
static constexpr int SM_MBAR = 1040;
static constexpr int SM_AHI  = 2048;
static constexpr int SM_ALO  = 34816;
static constexpr int SM_WHI  = 67584;
static constexpr int SM_WLO  = 133120;
static constexpr int SMEMG   = 198656;
static constexpr unsigned GEMM_IDESC =
    (1u << 4) | (1u << 7) | (1u << 10) | ((256u / 8) << 17) | (8u << 24);

template <bool RELU>
__global__ void __launch_bounds__(256) gemm_kernel(
    const float* __restrict__ A, const __nv_bfloat16* __restrict__ Whi,
    const __nv_bfloat16* __restrict__ Wlo, const float* __restrict__ bias,
    float* __restrict__ C, int K, int Kpad, int Ndir, size_t strideCz) {
    extern __shared__ char smem[];
    const int tid = threadIdx.x, wid = tid >> 5, lane = tid & 31;
    const int m0 = blockIdx.x * 128, n0 = blockIdx.y * 256, z = blockIdx.z;
    reinterpret_cast<float*>(smem)[tid] = bias[(size_t)z * Ndir + n0 + tid];
#if TC_OK
    const unsigned sb = smem_u32(smem);
    if (tid == 0) { MBAR_INIT(sb + SM_MBAR, 1); MBAR_INIT(sb + SM_MBAR + 8, 1); }
    if (wid == 0) { TC_ALLOC(sb + SM_TMEM, 256); TC_RELQ(); }
    __syncthreads();
    unsigned tmem;
    asm volatile("ld.shared.b32 %0, [%1];" : "=r"(tmem) : "r"(sb + SM_TMEM));
    const float* Ag = A + (size_t)m0 * K;
    const __nv_bfloat16* WhG = Whi + ((size_t)z * Ndir + n0) * Kpad;
    const __nv_bfloat16* WlG = Wlo + ((size_t)z * Ndir + n0) * Kpad;
    const int KT = Kpad / 64;
    int ph0 = 0, ph1 = 0;
    for (int kt = 0; kt < KT; ++kt) {
        const int b = kt & 1;
        if (kt >= 2) {
            if (b == 0) { mbar_wait(sb + SM_MBAR, ph0); ph0 ^= 1; }
            else        { mbar_wait(sb + SM_MBAR + 8, ph1); ph1 ^= 1; }
        }
        char* aHi = smem + SM_AHI + b * 16384;
        char* aLo = smem + SM_ALO + b * 16384;
        char* wHi = smem + SM_WHI + b * 32768;
        char* wLo = smem + SM_WLO + b * 32768;
        if ((K & 3) == 0) {
            for (int i = tid; i < 2048; i += 256) {
                int row = i >> 4, c4 = (i & 15) * 4;
                int kg = kt * 64 + c4;
                float4 v = make_float4(0.f, 0.f, 0.f, 0.f);
                if (kg < K) v = *reinterpret_cast<const float4*>(Ag + (size_t)row * K + kg);
                __nv_bfloat16 h0 = __float2bfloat16(v.x), h1 = __float2bfloat16(v.y);
                __nv_bfloat16 h2 = __float2bfloat16(v.z), h3 = __float2bfloat16(v.w);
                unsigned hiA = ((unsigned)__bfloat16_as_ushort(h1) << 16) | __bfloat16_as_ushort(h0);
                unsigned hiB = ((unsigned)__bfloat16_as_ushort(h3) << 16) | __bfloat16_as_ushort(h2);
                __nv_bfloat16 l0 = __float2bfloat16(v.x - __bfloat162float(h0));
                __nv_bfloat16 l1 = __float2bfloat16(v.y - __bfloat162float(h1));
                __nv_bfloat16 l2 = __float2bfloat16(v.z - __bfloat162float(h2));
                __nv_bfloat16 l3 = __float2bfloat16(v.w - __bfloat162float(h3));
                unsigned loA = ((unsigned)__bfloat16_as_ushort(l1) << 16) | __bfloat16_as_ushort(l0);
                unsigned loB = ((unsigned)__bfloat16_as_ushort(l3) << 16) | __bfloat16_as_ushort(l2);
                unsigned off = SWZ(row * 128 + c4 * 2);
                *reinterpret_cast<unsigned long long*>(aHi + off) =
                    ((unsigned long long)hiB << 32) | hiA;
                *reinterpret_cast<unsigned long long*>(aLo + off) =
                    ((unsigned long long)loB << 32) | loA;
            }
        } else {
            for (int i = tid; i < 8192; i += 256) {
                int row = i >> 6, c = i & 63;
                int kg = kt * 64 + c;
                float v = (kg < K) ? Ag[(size_t)row * K + kg] : 0.f;
                __nv_bfloat16 h, l; bfsplit(v, h, l);
                unsigned off = SWZ(row * 128 + c * 2);
                *reinterpret_cast<__nv_bfloat16*>(aHi + off) = h;
                *reinterpret_cast<__nv_bfloat16*>(aLo + off) = l;
            }
        }
        for (int i = tid; i < 2048; i += 256) {
            int n = i >> 3, c16 = i & 7;
            unsigned off = SWZ(n * 128 + c16 * 16);
            *reinterpret_cast<uint4*>(wHi + off) =
                *reinterpret_cast<const uint4*>(WhG + (size_t)n * Kpad + kt * 64 + c16 * 8);
            *reinterpret_cast<uint4*>(wLo + off) =
                *reinterpret_cast<const uint4*>(WlG + (size_t)n * Kpad + kt * 64 + c16 * 8);
        }
        FENCE_ASYNC();
        __syncthreads();
        if (wid == 0 && elect1()) {
            unsigned aH = sb + SM_AHI + b * 16384, aL = sb + SM_ALO + b * 16384;
            unsigned wH = sb + SM_WHI + b * 32768, wL = sb + SM_WLO + b * 32768;
            unsigned long long ads[3] = {mkdesc(aH), mkdesc(aL), mkdesc(aH)};
            unsigned long long bds[3] = {mkdesc(wH), mkdesc(wH), mkdesc(wL)};
#pragma unroll
            for (int s = 0; s < 3; ++s)
#pragma unroll
                for (int ks = 0; ks < 4; ++ks)
                    mma_f16_ss(tmem, ads[s] + ks * 2, bds[s] + ks * 2, GEMM_IDESC,
                               !(kt == 0 && s == 0 && ks == 0));
            TC_COMMIT(sb + SM_MBAR + b * 8);
        }
    }
    {
        const int bl = (KT - 1) & 1;
        mbar_wait(sb + SM_MBAR + bl * 8, bl ? ph1 : ph0);
    }
    TC_FENCE_AFTER();
    {
        const int row = (wid & 3) * 32 + lane;
        const int cb0 = (wid >> 2) * 128;
        const float* bs = reinterpret_cast<const float*>(smem);
        float* Crow = C + (size_t)z * strideCz + (size_t)(m0 + row) * Ndir + n0;
#pragma unroll
        for (int ch = 0; ch < 4; ++ch) {
            unsigned r[32];
            ldtm32(r, tmem + cb0 + ch * 32);
            TC_WAIT_LD();
            int cb = cb0 + ch * 32;
#pragma unroll
            for (int q = 0; q < 8; ++q) {
                float4 v;
                v.x = __uint_as_float(r[q * 4 + 0]) + bs[cb + q * 4 + 0];
                v.y = __uint_as_float(r[q * 4 + 1]) + bs[cb + q * 4 + 1];
                v.z = __uint_as_float(r[q * 4 + 2]) + bs[cb + q * 4 + 2];
                v.w = __uint_as_float(r[q * 4 + 3]) + bs[cb + q * 4 + 3];
                if (RELU) { v.x = reluf(v.x); v.y = reluf(v.y); v.z = reluf(v.z); v.w = reluf(v.w); }
                *reinterpret_cast<float4*>(Crow + cb + q * 4) = v;
            }
        }
    }
    __syncthreads();
    if (wid == 0) TC_DEALLOC(tmem, 256);
#else
    // naive fallback (plain-arch pass; sm_103a cubin is the one that runs)
    __syncthreads();
    const float* bs = reinterpret_cast<const float*>(smem);
    for (int e = tid; e < 128 * 256; e += 256) {
        int rr = e >> 8, n = e & 255;
        float acc = bs[n];
        const __nv_bfloat16* wh = Whi + ((size_t)z * Ndir + n0 + n) * Kpad;
        const __nv_bfloat16* wl = Wlo + ((size_t)z * Ndir + n0 + n) * Kpad;
        for (int k = 0; k < K; ++k)
            acc += A[(size_t)(m0 + rr) * K + k] *
                   (__bfloat162float(wh[k]) + __bfloat162float(wl[k]));
        if (RELU) acc = reluf(acc);
        C[(size_t)z * strideCz + (size_t)(m0 + rr) * Ndir + n0 + n] = acc;
    }
#endif
}

// ============ tensorized recurrent BiLSTM: block = 128 rows x 1 dir ============
template <int U>
__global__ void __launch_bounds__(256) lstm_rec_tc(
    const float* __restrict__ xz,          // [2][MBT][4U]
    const __nv_bfloat16* __restrict__ Uhi, // [2][4U][U]
    const __nv_bfloat16* __restrict__ Ulo,
    const float* __restrict__ Uf_raw, const float* __restrict__ Ub_raw,
    float* __restrict__ cst,               // [2][BATCH][U]
    float* __restrict__ out) {             // [MBT][2U]
    constexpr int KT = U / 64;
    constexpr int NALL = 4 * U;
    constexpr int HALVES = (NALL > 512) ? 2 : 1;
    constexpr int NH = NALL / HALVES;
    constexpr int NT = NH / 128;
    constexpr int AHI = 1024;
    constexpr int ALO = AHI + KT * 16384;
    constexpr int BHI = ALO + KT * 16384;
    constexpr int BLO = BHI + 16384;
    constexpr int SCR = BLO + 16384;
    extern __shared__ char smem[];
    const int tid = threadIdx.x, wid = tid >> 5, lane = tid & 31;
    const int dir = blockIdx.y;
    const int b0 = blockIdx.x * 128;
    const float* xzd = xz + (size_t)dir * MBT * NALL;
#if TC_OK
    const unsigned sb = smem_u32(smem);
    const __nv_bfloat16* UhD = Uhi + (size_t)dir * NALL * U;
    const __nv_bfloat16* UlD = Ulo + (size_t)dir * NALL * U;
    (void)Uf_raw; (void)Ub_raw;
    if (tid == 0) MBAR_INIT(sb + 16, 1);
    if (wid == 0) { TC_ALLOC(sb + 0, 512); TC_RELQ(); }
    __syncthreads();
    unsigned tmem;
    asm volatile("ld.shared.b32 %0, [%1];" : "=r"(tmem) : "r"(sb + 0));
    for (int i = tid * 16; i < 2 * KT * 16384; i += 256 * 16)
        *reinterpret_cast<uint4*>(smem + AHI + i) = make_uint4(0, 0, 0, 0);
    FENCE_ASYNC();
    __syncthreads();
    constexpr unsigned IDESC =
        (1u << 4) | (1u << 7) | (1u << 10) | ((128u / 8) << 17) | (8u << 24);
    int ph = 0;
    for (int step = 0; step < TT; ++step) {
        const int t = dir ? (TT - 1 - step) : step;
        for (int half = 0; half < HALVES; ++half) {
            const int nbase = half * 512;
            for (int kt = 0; kt < KT; ++kt) {
                for (int nt = 0; nt < NT; ++nt) {
                    const int nr0 = nbase + nt * 128;
                    for (int i = tid; i < 1024; i += 256) {
                        int rr = i >> 3, c16 = i & 7;
                        unsigned off = SWZ(rr * 128 + c16 * 16);
                        *reinterpret_cast<uint4*>(smem + BHI + off) =
                            *reinterpret_cast<const uint4*>(
                                UhD + (size_t)(nr0 + rr) * U + kt * 64 + c16 * 8);
                        *reinterpret_cast<uint4*>(smem + BLO + off) =
                            *reinterpret_cast<const uint4*>(
                                UlD + (size_t)(nr0 + rr) * U + kt * 64 + c16 * 8);
                    }
                    FENCE_ASYNC();
                    __syncthreads();
                    if (wid == 0 && elect1()) {
                        unsigned long long aH = mkdesc(sb + AHI + kt * 16384);
                        unsigned long long aL = mkdesc(sb + ALO + kt * 16384);
                        unsigned long long bH = mkdesc(sb + BHI);
                        unsigned long long bL = mkdesc(sb + BLO);
                        unsigned long long ads[3] = {aH, aL, aH};
                        unsigned long long bds[3] = {bH, bH, bL};
#pragma unroll
                        for (int s = 0; s < 3; ++s)
#pragma unroll
                            for (int ks = 0; ks < 4; ++ks)
                                mma_f16_ss(tmem + nt * 128, ads[s] + ks * 2,
                                           bds[s] + ks * 2, IDESC,
                                           !(kt == 0 && s == 0 && ks == 0));
                        TC_COMMIT(sb + 16);
                    }
                    __syncthreads();
                    mbar_wait(sb + 16, ph);
                    ph ^= 1;
                }
            }
            TC_FENCE_AFTER();
            {   // epilogue for this half
                const int row = (wid & 3) * 32 + lane;
                const int cg0 = (wid >> 2) * (NH / 2);
                const float* xzrow = xzd + ((size_t)(b0 + row) * TT + t) * NALL + nbase;
                float* crow = cst + ((size_t)dir * BATCH + b0 + row) * U;
                float* orow = out + ((size_t)(b0 + row) * TT + t) * (2 * U) + (size_t)dir * U;
#pragma unroll 1
                for (int ch = 0; ch < NH / 64; ++ch) {
                    int c0 = cg0 + ch * 32;
                    unsigned r[32];
                    ldtm32(r, tmem + c0);
                    TC_WAIT_LD();
                    int j0 = (nbase + c0) >> 2;
                    const float4* xp = reinterpret_cast<const float4*>(xzrow + c0);
                    float co[8];
                    if (step) {
                        float4 ca = *reinterpret_cast<const float4*>(crow + j0);
                        float4 cb2 = *reinterpret_cast<const float4*>(crow + j0 + 4);
                        co[0] = ca.x; co[1] = ca.y; co[2] = ca.z; co[3] = ca.w;
                        co[4] = cb2.x; co[5] = cb2.y; co[6] = cb2.z; co[7] = cb2.w;
                    } else {
#pragma unroll
                        for (int q = 0; q < 8; ++q) co[q] = 0.f;
                    }
                    float cn[8], hv[8];
                    unsigned hpk[8];
#pragma unroll
                    for (int q = 0; q < 8; ++q) {
                        float4 xa = xp[q];
                        float zi = __uint_as_float(r[q * 4 + 0]) + xa.x;
                        float zf = __uint_as_float(r[q * 4 + 1]) + xa.y;
                        float zg = __uint_as_float(r[q * 4 + 2]) + xa.z;
                        float zo = __uint_as_float(r[q * 4 + 3]) + xa.w;
                        cn[q] = sigf(zf) * co[q] + sigf(zi) * reluf(zg);
                        hv[q] = sigf(zo) * reluf(cn[q]);
                        __nv_bfloat16 hh, hl; bfsplit(hv[q], hh, hl);
                        hpk[q] = (unsigned)__bfloat16_as_ushort(hh) |
                                 ((unsigned)__bfloat16_as_ushort(hl) << 16);
                    }
                    *reinterpret_cast<float4*>(crow + j0) =
                        make_float4(cn[0], cn[1], cn[2], cn[3]);
                    *reinterpret_cast<float4*>(crow + j0 + 4) =
                        make_float4(cn[4], cn[5], cn[6], cn[7]);
                    *reinterpret_cast<float4*>(orow + j0) =
                        make_float4(hv[0], hv[1], hv[2], hv[3]);
                    *reinterpret_cast<float4*>(orow + j0 + 4) =
                        make_float4(hv[4], hv[5], hv[6], hv[7]);
                    if (HALVES == 2 && half == 0) {
                        uint4* s4 = reinterpret_cast<uint4*>(smem + SCR + (row * 128 + j0) * 4);
                        s4[0] = make_uint4(hpk[0], hpk[1], hpk[2], hpk[3]);
                        s4[1] = make_uint4(hpk[4], hpk[5], hpk[6], hpk[7]);
                    } else {
                        int jt = j0 >> 6, jc = j0 & 63;
                        unsigned off = SWZ(row * 128 + jc * 2);
                        unsigned hi[4], lo[4];
#pragma unroll
                        for (int q = 0; q < 4; ++q) {
                            hi[q] = (hpk[2 * q] & 0xffffu) | ((hpk[2 * q + 1] & 0xffffu) << 16);
                            lo[q] = (hpk[2 * q] >> 16) | ((hpk[2 * q + 1] >> 16) << 16);
                        }
                        *reinterpret_cast<uint4*>(smem + AHI + jt * 16384 + off) =
                            make_uint4(hi[0], hi[1], hi[2], hi[3]);
                        *reinterpret_cast<uint4*>(smem + ALO + jt * 16384 + off) =
                            make_uint4(lo[0], lo[1], lo[2], lo[3]);
                    }
                }
                TC_FENCE_BEFORE();
            }
            __syncthreads();
        }
        if (HALVES == 2) {   // flush half-0 h (units 0..127) from scratch into A
            for (int i = tid; i < 128 * 16; i += 256) {
                int row = i >> 4, j0 = (i & 15) * 8;
                const uint4* s4 =
                    reinterpret_cast<const uint4*>(smem + SCR + (row * 128 + j0) * 4);
                uint4 a = s4[0], b = s4[1];
                unsigned pk[8] = {a.x, a.y, a.z, a.w, b.x, b.y, b.z, b.w};
                unsigned hi[4], lo[4];
#pragma unroll
                for (int q = 0; q < 4; ++q) {
                    hi[q] = (pk[2 * q] & 0xffffu) | ((pk[2 * q + 1] & 0xffffu) << 16);
                    lo[q] = (pk[2 * q] >> 16) | ((pk[2 * q + 1] >> 16) << 16);
                }
                int jt = j0 >> 6, jc = j0 & 63;
                unsigned off = SWZ(row * 128 + jc * 2);
                *reinterpret_cast<uint4*>(smem + AHI + jt * 16384 + off) =
                    make_uint4(hi[0], hi[1], hi[2], hi[3]);
                *reinterpret_cast<uint4*>(smem + ALO + jt * 16384 + off) =
                    make_uint4(lo[0], lo[1], lo[2], lo[3]);
            }
        }
        FENCE_ASYNC();
        __syncthreads();
    }
    if (wid == 0) TC_DEALLOC(tmem, 512);
#else
    // naive fallback (never the executing cubin; correct + compilable)
    (void)Uhi; (void)Ulo;
    float* hs = reinterpret_cast<float*>(smem);   // [128][U]
    for (int i = tid; i < 128 * U; i += 256) hs[i] = 0.f;
    __syncthreads();
    const float* Uw = dir ? Ub_raw : Uf_raw;      // [U][4U]
    for (int step = 0; step < TT; ++step) {
        const int t = dir ? (TT - 1 - step) : step;
        if (tid < 128) {
            const int row = tid;
            const size_t m = (size_t)(b0 + row) * TT + t;
            float* crow = cst + ((size_t)dir * BATCH + b0 + row) * U;
            float* orow = out + m * (2 * U) + (size_t)dir * U;
            for (int j = 0; j < U; ++j) {
                float z[4];
                for (int g = 0; g < 4; ++g) {
                    float a = xzd[m * NALL + j * 4 + g];
                    for (int k = 0; k < U; ++k)
                        a += hs[row * U + k] * Uw[(size_t)k * 4 * U + g * U + j];
                    z[g] = a;
                }
                float co = step ? crow[j] : 0.f;
                float c2 = sigf(z[1]) * co + sigf(z[0]) * reluf(z[2]);
                float h = sigf(z[3]) * reluf(c2);
                crow[j] = c2; orow[j] = h;
            }
        }
        __syncthreads();
        if (tid < 128) {
            const size_t m = (size_t)(b0 + tid) * TT + t;
            for (int j = 0; j < U; ++j)
                hs[tid * U + j] = out[m * (2 * U) + (size_t)dir * U + j];
        }
        __syncthreads();
    }
#endif
}

// ================= tail =================
__global__ void __launch_bounds__(128) tail_kernel(
    const float* __restrict__ H1,
    const float* __restrict__ W2, const float* __restrict__ B2,
    const float* __restrict__ W3, const float* __restrict__ B3,
    const float* __restrict__ G, const float* __restrict__ Bb,
    const float* __restrict__ M, const float* __restrict__ V,
    const float* __restrict__ WO, const float* __restrict__ BO,
    float* __restrict__ Out) {
    __shared__ float h1s[4][256];
    __shared__ float h2s[4][128];
    __shared__ float h3s[4][64];
    int tid = threadIdx.x, lane = tid & 31, w = tid >> 5;
    int r0 = blockIdx.x * 4;
    for (int i = tid; i < 4 * 256; i += 128) h1s[i >> 8][i & 255] = H1[(size_t)r0 * 256 + i];
    __syncthreads();
    {
        int j = lane * 4;
        float4 bv = *reinterpret_cast<const float4*>(&B2[j]);
        float a0 = bv.x, a1 = bv.y, a2 = bv.z, a3 = bv.w;
#pragma unroll 4
        for (int k = 0; k < 256; k++) {
            float a = h1s[w][k];
            float4 wv = *reinterpret_cast<const float4*>(&W2[(size_t)k * 128 + j]);
            a0 += a * wv.x; a1 += a * wv.y; a2 += a * wv.z; a3 += a * wv.w;
        }
        h2s[w][j] = reluf(a0); h2s[w][j + 1] = reluf(a1);
        h2s[w][j + 2] = reluf(a2); h2s[w][j + 3] = reluf(a3);
    }
    __syncwarp();
    {
        int j = lane * 2;
        float a0 = B3[j], a1 = B3[j + 1];
#pragma unroll 4
        for (int k = 0; k < 128; k++) {
            float a = h2s[w][k];
            float2 wv = *reinterpret_cast<const float2*>(&W3[(size_t)k * 64 + j]);
            a0 += a * wv.x; a1 += a * wv.y;
        }
        a0 = reluf(a0); a1 = reluf(a1);
        float s0 = rsqrtf(V[j] + 1e-3f) * G[j];
        float s1 = rsqrtf(V[j + 1] + 1e-3f) * G[j + 1];
        h3s[w][j]     = (a0 - M[j]) * s0 + Bb[j];
        h3s[w][j + 1] = (a1 - M[j + 1]) * s1 + Bb[j + 1];
    }
    __syncwarp();
    float logit = -3.0e38f;
    if (lane < 26) {
        float a = BO[lane];
#pragma unroll 4
        for (int k = 0; k < 64; k++) a += h3s[w][k] * WO[(size_t)k * 26 + lane];
        logit = a;
    }
    float mx = logit;
#pragma unroll
    for (int o = 16; o; o >>= 1) mx = fmaxf(mx, __shfl_xor_sync(0xffffffffu, mx, o));
    float e = (lane < 26) ? __expf(logit - mx) : 0.f;
    float s = e;
#pragma unroll
    for (int o = 16; o; o >>= 1) s += __shfl_xor_sync(0xffffffffu, s, o);
    if (lane < 26) Out[(size_t)(r0 + w) * 26 + lane] = e * __fdividef(1.f, s);
}

// ================= launch =================
extern "C" void kernel_launch(void* const* d_in, const int* in_sizes, int n_in,
                              void* d_out, int out_size) {
    const float* x   = (const float*)d_in[0];
    const float* w1f = (const float*)d_in[1];
    const float* u1f = (const float*)d_in[2];
    const float* b1f = (const float*)d_in[3];
    const float* w1b = (const float*)d_in[4];
    const float* u1b = (const float*)d_in[5];
    const float* b1b = (const float*)d_in[6];
    const float* w2f = (const float*)d_in[7];
    const float* u2f = (const float*)d_in[8];
    const float* b2f = (const float*)d_in[9];
    const float* w2b = (const float*)d_in[10];
    const float* u2b = (const float*)d_in[11];
    const float* b2b = (const float*)d_in[12];
    const float* w3f = (const float*)d_in[13];
    const float* u3f = (const float*)d_in[14];
    const float* b3f = (const float*)d_in[15];
    const float* w3b = (const float*)d_in[16];
    const float* u3b = (const float*)d_in[17];
    const float* b3b = (const float*)d_in[18];
    const float* d1w = (const float*)d_in[19];
    const float* d1b = (const float*)d_in[20];
    const float* d2w = (const float*)d_in[21];
    const float* d2b = (const float*)d_in[22];
    const float* d3w = (const float*)d_in[23];
    const float* d3b = (const float*)d_in[24];
    const float* bng = (const float*)d_in[25];
    const float* bnb = (const float*)d_in[26];
    const float* bnm = (const float*)d_in[27];
    const float* bnv = (const float*)d_in[28];
    const float* ow  = (const float*)d_in[29];
    const float* ob  = (const float*)d_in[30];

    float *bufA, *bufB, *h1, *xz, *cst, *bg1, *bg2, *bg3;
    __nv_bfloat16 *uh1, *ul1, *uh2, *ul2, *uh3, *ul3;
    __nv_bfloat16 *w1h, *w1l, *w2h, *w2l, *w3h, *w3l, *wdh, *wdl;
    cudaGetSymbolAddress((void**)&bufA, g_bufA);
    cudaGetSymbolAddress((void**)&bufB, g_bufB);
    cudaGetSymbolAddress((void**)&h1, g_h1);
    cudaGetSymbolAddress((void**)&xz, g_xz);
    cudaGetSymbolAddress((void**)&cst, g_c);
    cudaGetSymbolAddress((void**)&bg1, g_bg1);
    cudaGetSymbolAddress((void**)&bg2, g_bg2);
    cudaGetSymbolAddress((void**)&bg3, g_bg3);
    cudaGetSymbolAddress((void**)&uh1, g_uh1);
    cudaGetSymbolAddress((void**)&ul1, g_ul1);
    cudaGetSymbolAddress((void**)&uh2, g_uh2);
    cudaGetSymbolAddress((void**)&ul2, g_ul2);
    cudaGetSymbolAddress((void**)&uh3, g_uh3);
    cudaGetSymbolAddress((void**)&ul3, g_ul3);
    cudaGetSymbolAddress((void**)&w1h, g_w1h);
    cudaGetSymbolAddress((void**)&w1l, g_w1l);
    cudaGetSymbolAddress((void**)&w2h, g_w2h);
    cudaGetSymbolAddress((void**)&w2l, g_w2l);
    cudaGetSymbolAddress((void**)&w3h, g_w3h);
    cudaGetSymbolAddress((void**)&w3l, g_w3l);
    cudaGetSymbolAddress((void**)&wdh, g_wdh);
    cudaGetSymbolAddress((void**)&wdl, g_wdl);

    cudaFuncSetAttribute(gemm_kernel<false>, cudaFuncAttributeMaxDynamicSharedMemorySize, SMEMG);
    cudaFuncSetAttribute(gemm_kernel<true>,  cudaFuncAttributeMaxDynamicSharedMemorySize, SMEMG);
    const int r1 = 66560, r2 = 99328, r3 = 230400;   // rec smem sizes
    cudaFuncSetAttribute(lstm_rec_tc<64>,  cudaFuncAttributeMaxDynamicSharedMemorySize, r1);
    cudaFuncSetAttribute(lstm_rec_tc<128>, cudaFuncAttributeMaxDynamicSharedMemorySize, r2);
    cudaFuncSetAttribute(lstm_rec_tc<256>, cudaFuncAttributeMaxDynamicSharedMemorySize, r3);

    prep_lstm<<<512, 256>>>(u1f, u1b, u2f, u2b, u3f, u3b,
                            w1f, w1b, w2f, w2b, w3f, w3b,
                            b1f, b1b, b2f, b2b, b3f, b3b);
    prep_dense<<<512, 256>>>(d1w);

    // L1
    gemm_kernel<false><<<dim3(MBT / 128, 1, 2), 256, SMEMG>>>(
        x, w1h, w1l, bg1, xz, 126, 128, 256, (size_t)MBT * 256);
    lstm_rec_tc<64><<<dim3(BATCH / 128, 2), 256, r1>>>(xz, uh1, ul1, u1f, u1b, cst, bufA);
    // L2
    gemm_kernel<false><<<dim3(MBT / 128, 2, 2), 256, SMEMG>>>(
        bufA, w2h, w2l, bg2, xz, 128, 128, 512, (size_t)MBT * 512);
    lstm_rec_tc<128><<<dim3(BATCH / 128, 2), 256, r2>>>(xz, uh2, ul2, u2f, u2b, cst, bufB);
    // L3
    gemm_kernel<false><<<dim3(MBT / 128, 4, 2), 256, SMEMG>>>(
        bufB, w3h, w3l, bg3, xz, 256, 256, 1024, (size_t)MBT * 1024);
    lstm_rec_tc<256><<<dim3(BATCH / 128, 2), 256, r3>>>(xz, uh3, ul3, u3f, u3b, cst, bufA);
    // dense1 (M=8192, K=15360, N=256) + relu
    gemm_kernel<true><<<dim3(BATCH / 128, 1, 1), 256, SMEMG>>>(
        bufA, wdh, wdl, d1b, h1, 15360, 15360, 256, 0);
    tail_kernel<<<BATCH / 4, 128>>>(h1, d2w, d2b, d3w, d3b, bng, bnb, bnm, bnv, ow, ob,
                                    (float*)d_out);
    (void)in_sizes; (void)n_in; (void)out_size;
}

// round 12
// speedup vs baseline: 1.2949x; 1.0697x over previous
#include <cuda_runtime.h>
#include <cuda_bf16.h>
#include <cstdint>

#define DEVFN __device__ __forceinline__

#if defined(__CUDA_ARCH_FEAT_SM103_ALL) || defined(__CUDA_ARCH_FEAT_SM100_ALL) || \
    defined(__CUDA_ARCH_FEAT_SM101_ALL) || defined(__CUDA_ARCH_SPECIFIC__) ||     \
    defined(__CUDA_ARCH_FAMILY_SPECIFIC__)
#define TC_OK 1
#else
#define TC_OK 0
#endif

DEVFN float sigf(float x) { return __fdividef(1.f, 1.f + __expf(-x)); }
DEVFN float reluf(float x) { return fmaxf(x, 0.f); }

static constexpr int BATCH = 8192;
static constexpr int TT    = 30;
static constexpr int MBT   = BATCH * TT;   // 245760

// ================= scratch (static __device__, no allocation) =================
__device__ float g_bufA[(size_t)MBT * 512];
__device__ float g_bufB[(size_t)MBT * 256];
__device__ float g_h1[(size_t)BATCH * 256];
__device__ float g_xz[(size_t)2 * MBT * 1024];
__device__ float g_c[(size_t)2 * BATCH * 256];
__device__ __align__(128) __nv_bfloat16 g_uh1[2 * 256 * 64],   g_ul1[2 * 256 * 64];
__device__ __align__(128) __nv_bfloat16 g_uh2[2 * 512 * 128],  g_ul2[2 * 512 * 128];
__device__ __align__(128) __nv_bfloat16 g_uh3[2 * 1024 * 256], g_ul3[2 * 1024 * 256];
__device__ __align__(128) __nv_bfloat16 g_w1h[2 * 256 * 128],  g_w1l[2 * 256 * 128];
__device__ __align__(128) __nv_bfloat16 g_w2h[2 * 512 * 128],  g_w2l[2 * 512 * 128];
__device__ __align__(128) __nv_bfloat16 g_w3h[2 * 1024 * 256], g_w3l[2 * 1024 * 256];
__device__ __align__(128) __nv_bfloat16 g_wdh[256 * 15360],    g_wdl[256 * 15360];
__device__ float g_bg1[512], g_bg2[1024], g_bg3[2048];

// ================= tcgen05 helpers (guarded) =================
DEVFN unsigned smem_u32(const void* p) {
    unsigned a;
    asm("{ .reg .u64 t; cvta.to.shared.u64 t, %1; cvt.u32.u64 %0, t; }" : "=r"(a) : "l"(p));
    return a;
}
#if TC_OK
DEVFN unsigned elect1() {
    unsigned p;
    asm("{\n\t.reg .pred p;\n\telect.sync _|p, 0xFFFFFFFF;\n\tselp.b32 %0, 1, 0, p;\n\t}" : "=r"(p));
    return p;
}
#define SWZ(x) ((x) ^ (((x) >> 3) & 0x70))
static constexpr unsigned long long DESC_BASE =
    (2ull << 61) | (1ull << 46) | (64ull << 32) | (1ull << 16);
DEVFN unsigned long long mkdesc(unsigned a) { return DESC_BASE | ((a >> 4) & 0x3FFF); }
DEVFN void mma_f16_ss(unsigned d, unsigned long long ad, unsigned long long bd,
                      unsigned idesc, unsigned en) {
    asm volatile(
        "{\n\t.reg .pred p;\n\tsetp.ne.u32 p, %5, 0;\n\t"
        "tcgen05.mma.cta_group::1.kind::f16 [%0], %1, %2, %3, {%4, %4, %4, %4}, p;\n\t}"
        :: "r"(d), "l"(ad), "l"(bd), "r"(idesc), "r"(0u), "r"(en) : "memory");
}
#define TC_ALLOC(sm, n) \
    asm volatile("tcgen05.alloc.cta_group::1.sync.aligned.shared::cta.b32 [%0], %1;" :: "r"(sm), "r"(n) : "memory")
#define TC_RELQ() asm volatile("tcgen05.relinquish_alloc_permit.cta_group::1.sync.aligned;")
#define TC_DEALLOC(t, n) asm volatile("tcgen05.dealloc.cta_group::1.sync.aligned.b32 %0, %1;" :: "r"(t), "r"(n))
#define TC_COMMIT(mb) \
    asm volatile("tcgen05.commit.cta_group::1.mbarrier::arrive::one.shared::cluster.b64 [%0];" :: "r"(mb) : "memory")
#define TC_FENCE_AFTER() asm volatile("tcgen05.fence::after_thread_sync;" ::: "memory")
#define TC_FENCE_BEFORE() asm volatile("tcgen05.fence::before_thread_sync;" ::: "memory")
#define TC_WAIT_LD() asm volatile("tcgen05.wait::ld.sync.aligned;" ::: "memory")
#define FENCE_ASYNC() asm volatile("fence.proxy.async.shared::cta;" ::: "memory")
#define MBAR_INIT(mb, c) asm volatile("mbarrier.init.shared.b64 [%0], %1;" :: "r"(mb), "r"(c) : "memory")
DEVFN void mbar_wait(unsigned mb, unsigned parity) {
    asm volatile(
        "{\n\t.reg .pred P;\n\t"
        "W_%=:\n\t"
        "mbarrier.try_wait.parity.acquire.cta.shared::cta.b64 P, [%0], %1, 0x989680;\n\t"
        "@P bra.uni D_%=;\n\t"
        "bra.uni W_%=;\n\t"
        "D_%=:\n\t}"
        :: "r"(mb), "r"(parity) : "memory");
}
DEVFN void ldtm32(unsigned* r, unsigned a) {
    asm volatile(
        "tcgen05.ld.sync.aligned.32x32b.x32.b32 "
        "{%0,%1,%2,%3,%4,%5,%6,%7,%8,%9,%10,%11,%12,%13,%14,%15,"
        "%16,%17,%18,%19,%20,%21,%22,%23,%24,%25,%26,%27,%28,%29,%30,%31}, [%32];"
        : "=r"(r[0]), "=r"(r[1]), "=r"(r[2]), "=r"(r[3]), "=r"(r[4]), "=r"(r[5]),
          "=r"(r[6]), "=r"(r[7]), "=r"(r[8]), "=r"(r[9]), "=r"(r[10]), "=r"(r[11]),
          "=r"(r[12]), "=r"(r[13]), "=r"(r[14]), "=r"(r[15]), "=r"(r[16]), "=r"(r[17]),
          "=r"(r[18]), "=r"(r[19]), "=r"(r[20]), "=r"(r[21]), "=r"(r[22]), "=r"(r[23]),
          "=r"(r[24]), "=r"(r[25]), "=r"(r[26]), "=r"(r[27]), "=r"(r[28]), "=r"(r[29]),
          "=r"(r[30]), "=r"(r[31])
        : "r"(a));
}
#endif  // TC_OK

// ================= prep =================
DEVFN void bfsplit(float v, __nv_bfloat16& hi, __nv_bfloat16& lo) {
    hi = __float2bfloat16(v);
    lo = __float2bfloat16(v - __bfloat162float(hi));
}
DEVFN void utc1(long i, const float* Uf, const float* Ub, __nv_bfloat16* hi,
                __nv_bfloat16* lo, int U) {
    long per = (long)4 * U * U;
    int d = i >= per; i -= (long)d * per;
    int k = (int)(i % U); long n = i / U;
    int g = (int)(n & 3); int j = (int)(n >> 2);
    float v = (d ? Ub : Uf)[(size_t)k * 4 * U + g * U + j];
    __nv_bfloat16 h, l; bfsplit(v, h, l);
    hi[(size_t)d * per + i] = h;
    lo[(size_t)d * per + i] = l;
}
DEVFN void wsplit1(long i, const float* Wf, const float* Wb, __nv_bfloat16* hi,
                   __nv_bfloat16* lo, int DIN, int U, int Kpad) {
    long per = (long)4 * U * Kpad;
    int d = i >= per; i -= (long)d * per;
    int kp = (int)(i % Kpad); long n = i / Kpad;
    int g = (int)(n & 3); int j = (int)(n >> 2);
    float v = (kp < DIN) ? (d ? Wb : Wf)[(size_t)kp * 4 * U + g * U + j] : 0.f;
    __nv_bfloat16 h, l; bfsplit(v, h, l);
    hi[(size_t)d * per + i] = h;
    lo[(size_t)d * per + i] = l;
}
DEVFN void bpack1(long i, const float* bf_, const float* bb_, float* dst, int U) {
    int N = 4 * U;
    int d = i >= N; i -= (long)d * N;
    int g = (int)(i & 3); int j = (int)(i >> 2);
    dst[(size_t)d * N + i] = (d ? bb_ : bf_)[g * U + j];
}

__global__ void prep_lstm(
    const float* u1f, const float* u1b, const float* u2f, const float* u2b,
    const float* u3f, const float* u3b,
    const float* w1f, const float* w1b, const float* w2f, const float* w2b,
    const float* w3f, const float* w3b,
    const float* b1f, const float* b1b, const float* b2f, const float* b2b,
    const float* b3f, const float* b3b) {
    constexpr long G1 = 2L * 256 * 64, G2 = 2L * 512 * 128, G3 = 2L * 1024 * 256;
    constexpr long C3 = 2L * 256 * 128, C4 = 2L * 512 * 128, C5 = 2L * 1024 * 256;
    const long total = G1 + G2 + G3 + C3 + C4 + C5 + 2L * (256 + 512 + 1024);
    for (long idx = blockIdx.x * (long)blockDim.x + threadIdx.x; idx < total;
         idx += (long)gridDim.x * blockDim.x) {
        long i = idx;
        if (i < G1) { utc1(i, u1f, u1b, g_uh1, g_ul1, 64); continue; } i -= G1;
        if (i < G2) { utc1(i, u2f, u2b, g_uh2, g_ul2, 128); continue; } i -= G2;
        if (i < G3) { utc1(i, u3f, u3b, g_uh3, g_ul3, 256); continue; } i -= G3;
        if (i < C3) { wsplit1(i, w1f, w1b, g_w1h, g_w1l, 126, 64, 128); continue; } i -= C3;
        if (i < C4) { wsplit1(i, w2f, w2b, g_w2h, g_w2l, 128, 128, 128); continue; } i -= C4;
        if (i < C5) { wsplit1(i, w3f, w3b, g_w3h, g_w3l, 256, 256, 256); continue; } i -= C5;
        if (i < 512) { bpack1(i, b1f, b1b, g_bg1, 64); continue; } i -= 512;
        if (i < 1024) { bpack1(i, b2f, b2b, g_bg2, 128); continue; } i -= 1024;
        bpack1(i, b3f, b3b, g_bg3, 256);
    }
}

__global__ void prep_dense(const float* __restrict__ W) {
    const long total = 256L * 15360;
    for (long idx = blockIdx.x * (long)blockDim.x + threadIdx.x; idx < total;
         idx += (long)gridDim.x * blockDim.x) {
        int n = (int)(idx / 15360), k = (int)(idx % 15360);
        __nv_bfloat16 h, l; bfsplit(W[(size_t)k * 256 + n], h, l);
        g_wdh[idx] = h;
        g_wdl[idx] = l;
    }
}

// ================= GEMM: C[z] = A @ W[z] + bias[z] (opt relu) ==================
static constexpr int SM_TMEM = 1024;
static constexpr int SM_MBAR = 1040;
static constexpr int SM_AHI  = 2048;
static constexpr int SM_ALO  = 34816;
static constexpr int SM_WHI  = 67584;
static constexpr int SM_WLO  = 133120;
static constexpr int SMEMG   = 198656;
static constexpr unsigned GEMM_IDESC =
    (1u << 4) | (1u << 7) | (1u << 10) | ((256u / 8) << 17) | (8u << 24);

template <bool RELU>
__global__ void __launch_bounds__(256) gemm_kernel(
    const float* __restrict__ A, const __nv_bfloat16* __restrict__ Whi,
    const __nv_bfloat16* __restrict__ Wlo, const float* __restrict__ bias,
    float* __restrict__ C, int K, int Kpad, int Ndir, size_t strideCz) {
    extern __shared__ char smem[];
    const int tid = threadIdx.x, wid = tid >> 5, lane = tid & 31;
    const int m0 = blockIdx.x * 128, n0 = blockIdx.y * 256, z = blockIdx.z;
    reinterpret_cast<float*>(smem)[tid] = bias[(size_t)z * Ndir + n0 + tid];
#if TC_OK
    const unsigned sb = smem_u32(smem);
    if (tid == 0) { MBAR_INIT(sb + SM_MBAR, 1); MBAR_INIT(sb + SM_MBAR + 8, 1); }
    if (wid == 0) { TC_ALLOC(sb + SM_TMEM, 256); TC_RELQ(); }
    __syncthreads();
    unsigned tmem;
    asm volatile("ld.shared.b32 %0, [%1];" : "=r"(tmem) : "r"(sb + SM_TMEM));
    const float* Ag = A + (size_t)m0 * K;
    const __nv_bfloat16* WhG = Whi + ((size_t)z * Ndir + n0) * Kpad;
    const __nv_bfloat16* WlG = Wlo + ((size_t)z * Ndir + n0) * Kpad;
    const int KT = Kpad / 64;
    int ph0 = 0, ph1 = 0;
    for (int kt = 0; kt < KT; ++kt) {
        const int b = kt & 1;
        if (kt >= 2) {
            if (b == 0) { mbar_wait(sb + SM_MBAR, ph0); ph0 ^= 1; }
            else        { mbar_wait(sb + SM_MBAR + 8, ph1); ph1 ^= 1; }
        }
        char* aHi = smem + SM_AHI + b * 16384;
        char* aLo = smem + SM_ALO + b * 16384;
        char* wHi = smem + SM_WHI + b * 32768;
        char* wLo = smem + SM_WLO + b * 32768;
        if ((K & 3) == 0) {
            for (int i = tid; i < 2048; i += 256) {
                int row = i >> 4, c4 = (i & 15) * 4;
                int kg = kt * 64 + c4;
                float4 v = make_float4(0.f, 0.f, 0.f, 0.f);
                if (kg < K) v = *reinterpret_cast<const float4*>(Ag + (size_t)row * K + kg);
                __nv_bfloat16 h0 = __float2bfloat16(v.x), h1 = __float2bfloat16(v.y);
                __nv_bfloat16 h2 = __float2bfloat16(v.z), h3 = __float2bfloat16(v.w);
                unsigned hiA = ((unsigned)__bfloat16_as_ushort(h1) << 16) | __bfloat16_as_ushort(h0);
                unsigned hiB = ((unsigned)__bfloat16_as_ushort(h3) << 16) | __bfloat16_as_ushort(h2);
                __nv_bfloat16 l0 = __float2bfloat16(v.x - __bfloat162float(h0));
                __nv_bfloat16 l1 = __float2bfloat16(v.y - __bfloat162float(h1));
                __nv_bfloat16 l2 = __float2bfloat16(v.z - __bfloat162float(h2));
                __nv_bfloat16 l3 = __float2bfloat16(v.w - __bfloat162float(h3));
                unsigned loA = ((unsigned)__bfloat16_as_ushort(l1) << 16) | __bfloat16_as_ushort(l0);
                unsigned loB = ((unsigned)__bfloat16_as_ushort(l3) << 16) | __bfloat16_as_ushort(l2);
                unsigned off = SWZ(row * 128 + c4 * 2);
                *reinterpret_cast<unsigned long long*>(aHi + off) =
                    ((unsigned long long)hiB << 32) | hiA;
                *reinterpret_cast<unsigned long long*>(aLo + off) =
                    ((unsigned long long)loB << 32) | loA;
            }
        } else {
            for (int i = tid; i < 8192; i += 256) {
                int row = i >> 6, c = i & 63;
                int kg = kt * 64 + c;
                float v = (kg < K) ? Ag[(size_t)row * K + kg] : 0.f;
                __nv_bfloat16 h, l; bfsplit(v, h, l);
                unsigned off = SWZ(row * 128 + c * 2);
                *reinterpret_cast<__nv_bfloat16*>(aHi + off) = h;
                *reinterpret_cast<__nv_bfloat16*>(aLo + off) = l;
            }
        }
        for (int i = tid; i < 2048; i += 256) {
            int n = i >> 3, c16 = i & 7;
            unsigned off = SWZ(n * 128 + c16 * 16);
            *reinterpret_cast<uint4*>(wHi + off) =
                *reinterpret_cast<const uint4*>(WhG + (size_t)n * Kpad + kt * 64 + c16 * 8);
            *reinterpret_cast<uint4*>(wLo + off) =
                *reinterpret_cast<const uint4*>(WlG + (size_t)n * Kpad + kt * 64 + c16 * 8);
        }
        FENCE_ASYNC();
        __syncthreads();
        if (wid == 0 && elect1()) {
            unsigned aH = sb + SM_AHI + b * 16384, aL = sb + SM_ALO + b * 16384;
            unsigned wH = sb + SM_WHI + b * 32768, wL = sb + SM_WLO + b * 32768;
            unsigned long long ads[3] = {mkdesc(aH), mkdesc(aL), mkdesc(aH)};
            unsigned long long bds[3] = {mkdesc(wH), mkdesc(wH), mkdesc(wL)};
#pragma unroll
            for (int s = 0; s < 3; ++s)
#pragma unroll
                for (int ks = 0; ks < 4; ++ks)
                    mma_f16_ss(tmem, ads[s] + ks * 2, bds[s] + ks * 2, GEMM_IDESC,
                               !(kt == 0 && s == 0 && ks == 0));
            TC_COMMIT(sb + SM_MBAR + b * 8);
        }
    }
    {
        const int bl = (KT - 1) & 1;
        mbar_wait(sb + SM_MBAR + bl * 8, bl ? ph1 : ph0);
    }
    TC_FENCE_AFTER();
    {
        const int row = (wid & 3) * 32 + lane;
        const int cb0 = (wid >> 2) * 128;
        const float* bs = reinterpret_cast<const float*>(smem);
        float* Crow = C + (size_t)z * strideCz + (size_t)(m0 + row) * Ndir + n0;
#pragma unroll
        for (int ch = 0; ch < 4; ++ch) {
            unsigned r[32];
            ldtm32(r, tmem + cb0 + ch * 32);
            TC_WAIT_LD();
            int cb = cb0 + ch * 32;
#pragma unroll
            for (int q = 0; q < 8; ++q) {
                float4 v;
                v.x = __uint_as_float(r[q * 4 + 0]) + bs[cb + q * 4 + 0];
                v.y = __uint_as_float(r[q * 4 + 1]) + bs[cb + q * 4 + 1];
                v.z = __uint_as_float(r[q * 4 + 2]) + bs[cb + q * 4 + 2];
                v.w = __uint_as_float(r[q * 4 + 3]) + bs[cb + q * 4 + 3];
                if (RELU) { v.x = reluf(v.x); v.y = reluf(v.y); v.z = reluf(v.z); v.w = reluf(v.w); }
                *reinterpret_cast<float4*>(Crow + cb + q * 4) = v;
            }
        }
    }
    __syncthreads();
    if (wid == 0) TC_DEALLOC(tmem, 256);
#else
    __syncthreads();
    const float* bs = reinterpret_cast<const float*>(smem);
    for (int e = tid; e < 128 * 256; e += 256) {
        int rr = e >> 8, n = e & 255;
        float acc = bs[n];
        const __nv_bfloat16* wh = Whi + ((size_t)z * Ndir + n0 + n) * Kpad;
        const __nv_bfloat16* wl = Wlo + ((size_t)z * Ndir + n0 + n) * Kpad;
        for (int k = 0; k < K; ++k)
            acc += A[(size_t)(m0 + rr) * K + k] *
                   (__bfloat162float(wh[k]) + __bfloat162float(wl[k]));
        if (RELU) acc = reluf(acc);
        C[(size_t)z * strideCz + (size_t)(m0 + rr) * Ndir + n0 + n] = acc;
    }
#endif
}

// ====== tensorized recurrent BiLSTM, pipelined: block = 128 rows x 1 dir ======
template <int U>
__global__ void __launch_bounds__(256) lstm_rec_tc(
    const float* __restrict__ xz,          // [2][MBT][4U]
    const __nv_bfloat16* __restrict__ Uhi, // [2][4U][U]
    const __nv_bfloat16* __restrict__ Ulo,
    const float* __restrict__ Uf_raw, const float* __restrict__ Ub_raw,
    float* __restrict__ cst,               // [2][BATCH][U]
    float* __restrict__ out) {             // [MBT][2U]
    constexpr int KT = U / 64;
    constexpr int NALL = 4 * U;
    constexpr int HALVES = (NALL > 512) ? 2 : 1;
    constexpr int NH = NALL / HALVES;
    constexpr int NT = NH / 128;
    constexpr int ITERS = KT * NT;
    constexpr bool STREAM = (U > 64);
    constexpr int AHI = 1024;
    constexpr int ALO = AHI + KT * 16384;
    constexpr int BB  = ALO + KT * 16384;
    constexpr int TMC = (NALL < 512) ? NALL : 512;
    extern __shared__ char smem[];
    const int tid = threadIdx.x, wid = tid >> 5, lane = tid & 31;
    const int dir = blockIdx.y;
    const int b0 = blockIdx.x * 128;
    const float* xzd = xz + (size_t)dir * MBT * NALL;
#if TC_OK
    const unsigned sb = smem_u32(smem);
    const __nv_bfloat16* UhD = Uhi + (size_t)dir * NALL * U;
    const __nv_bfloat16* UlD = Ulo + (size_t)dir * NALL * U;
    (void)Uf_raw; (void)Ub_raw;
    if (tid == 0) { MBAR_INIT(sb + 16, 1); MBAR_INIT(sb + 24, 1); }
    if (wid == 0) { TC_ALLOC(sb + 0, TMC); TC_RELQ(); }
    __syncthreads();
    unsigned tmem;
    asm volatile("ld.shared.b32 %0, [%1];" : "=r"(tmem) : "r"(sb + 0));
    for (int i = tid * 16; i < 2 * KT * 16384; i += 256 * 16)
        *reinterpret_cast<uint4*>(smem + AHI + i) = make_uint4(0, 0, 0, 0);
    if (!STREAM) {   // resident B: both 128-row tiles staged once
        for (int i = tid; i < 2048; i += 256) {
            int bb = i >> 10, rr = (i >> 3) & 127, c16 = i & 7;
            int nr = bb * 128 + rr;
            unsigned off = SWZ(rr * 128 + c16 * 16);
            *reinterpret_cast<uint4*>(smem + BB + bb * 32768 + off) =
                *reinterpret_cast<const uint4*>(UhD + (size_t)nr * U + c16 * 8);
            *reinterpret_cast<uint4*>(smem + BB + bb * 32768 + 16384 + off) =
                *reinterpret_cast<const uint4*>(UlD + (size_t)nr * U + c16 * 8);
        }
    }
    FENCE_ASYNC();
    __syncthreads();
    constexpr unsigned IDESC =
        (1u << 4) | (1u << 7) | (1u << 10) | ((128u / 8) << 17) | (8u << 24);
    int wc0 = 0, wc1 = 0;
    for (int step = 0; step < TT; ++step) {
        const int t = dir ? (TT - 1 - step) : step;
        for (int half = 0; half < HALVES; ++half) {
            const int nbase = half * NH;
            if (STREAM) {
                for (int i = 0; i < ITERS; ++i) {
                    const int b = i & 1;
                    if (i >= 2) {
                        if (b == 0) { mbar_wait(sb + 16, wc0 & 1); wc0++; }
                        else        { mbar_wait(sb + 24, wc1 & 1); wc1++; }
                    }
                    const int kt = i / NT, nt = i % NT;
                    const int nr0 = nbase + nt * 128;
                    for (int ii = tid; ii < 1024; ii += 256) {
                        int rr = ii >> 3, c16 = ii & 7;
                        unsigned off = SWZ(rr * 128 + c16 * 16);
                        *reinterpret_cast<uint4*>(smem + BB + b * 32768 + off) =
                            *reinterpret_cast<const uint4*>(
                                UhD + (size_t)(nr0 + rr) * U + kt * 64 + c16 * 8);
                        *reinterpret_cast<uint4*>(smem + BB + b * 32768 + 16384 + off) =
                            *reinterpret_cast<const uint4*>(
                                UlD + (size_t)(nr0 + rr) * U + kt * 64 + c16 * 8);
                    }
                    FENCE_ASYNC();
                    __syncthreads();
                    if (wid == 0 && elect1()) {
                        unsigned long long aH = mkdesc(sb + AHI + kt * 16384);
                        unsigned long long aL = mkdesc(sb + ALO + kt * 16384);
                        unsigned long long bH = mkdesc(sb + BB + b * 32768);
                        unsigned long long bL = mkdesc(sb + BB + b * 32768 + 16384);
                        unsigned long long ads[3] = {aH, aL, aH};
                        unsigned long long bds[3] = {bH, bH, bL};
#pragma unroll
                        for (int s = 0; s < 3; ++s)
#pragma unroll
                            for (int ks = 0; ks < 4; ++ks)
                                mma_f16_ss(tmem + nt * 128, ads[s] + ks * 2,
                                           bds[s] + ks * 2, IDESC,
                                           !(kt == 0 && s == 0 && ks == 0));
                        TC_COMMIT(sb + 16 + 8 * b);
                    }
                }
                mbar_wait(sb + 16, wc0 & 1); wc0++;   // drain (ITERS even)
                mbar_wait(sb + 24, wc1 & 1); wc1++;
            } else {
                if (wid == 0 && elect1()) {
                    unsigned long long aH = mkdesc(sb + AHI);
                    unsigned long long aL = mkdesc(sb + ALO);
#pragma unroll
                    for (int nt = 0; nt < NT; ++nt) {
                        unsigned long long bH = mkdesc(sb + BB + nt * 32768);
                        unsigned long long bL = mkdesc(sb + BB + nt * 32768 + 16384);
                        unsigned long long ads[3] = {aH, aL, aH};
                        unsigned long long bds[3] = {bH, bH, bL};
#pragma unroll
                        for (int s = 0; s < 3; ++s)
#pragma unroll
                            for (int ks = 0; ks < 4; ++ks)
                                mma_f16_ss(tmem + nt * 128, ads[s] + ks * 2,
                                           bds[s] + ks * 2, IDESC,
                                           !(s == 0 && ks == 0));
                    }
                    TC_COMMIT(sb + 16);
                }
                mbar_wait(sb + 16, wc0 & 1); wc0++;
            }
            TC_FENCE_AFTER();
            {   // epilogue for this half
                const int row = (wid & 3) * 32 + lane;
                const int cg0 = (wid >> 2) * (NH / 2);
                const float* xzrow = xzd + ((size_t)(b0 + row) * TT + t) * NALL + nbase;
                float* crow = cst + ((size_t)dir * BATCH + b0 + row) * U;
                float* orow = out + ((size_t)(b0 + row) * TT + t) * (2 * U) + (size_t)dir * U;
#pragma unroll 1
                for (int ch = 0; ch < NH / 64; ++ch) {
                    int c0 = cg0 + ch * 32;
                    unsigned r[32];
                    ldtm32(r, tmem + c0);
                    TC_WAIT_LD();
                    int j0 = (nbase + c0) >> 2;
                    const float4* xp = reinterpret_cast<const float4*>(xzrow + c0);
                    float co[8];
                    if (step) {
                        float4 ca = *reinterpret_cast<const float4*>(crow + j0);
                        float4 cb2 = *reinterpret_cast<const float4*>(crow + j0 + 4);
                        co[0] = ca.x; co[1] = ca.y; co[2] = ca.z; co[3] = ca.w;
                        co[4] = cb2.x; co[5] = cb2.y; co[6] = cb2.z; co[7] = cb2.w;
                    } else {
#pragma unroll
                        for (int q = 0; q < 8; ++q) co[q] = 0.f;
                    }
                    float cn[8], hv[8];
#pragma unroll
                    for (int q = 0; q < 8; ++q) {
                        float4 xa = xp[q];
                        float zi = __uint_as_float(r[q * 4 + 0]) + xa.x;
                        float zf = __uint_as_float(r[q * 4 + 1]) + xa.y;
                        float zg = __uint_as_float(r[q * 4 + 2]) + xa.z;
                        float zo = __uint_as_float(r[q * 4 + 3]) + xa.w;
                        cn[q] = sigf(zf) * co[q] + sigf(zi) * reluf(zg);
                        hv[q] = sigf(zo) * reluf(cn[q]);
                    }
                    *reinterpret_cast<float4*>(crow + j0) =
                        make_float4(cn[0], cn[1], cn[2], cn[3]);
                    *reinterpret_cast<float4*>(crow + j0 + 4) =
                        make_float4(cn[4], cn[5], cn[6], cn[7]);
                    *reinterpret_cast<float4*>(orow + j0) =
                        make_float4(hv[0], hv[1], hv[2], hv[3]);
                    *reinterpret_cast<float4*>(orow + j0 + 4) =
                        make_float4(hv[4], hv[5], hv[6], hv[7]);
                    if (!(HALVES == 2 && half == 0)) {   // write h into A tiles
                        unsigned hi[4], lo[4];
#pragma unroll
                        for (int q = 0; q < 4; ++q) {
                            __nv_bfloat16 h0, l0, h1, l1;
                            bfsplit(hv[2 * q], h0, l0);
                            bfsplit(hv[2 * q + 1], h1, l1);
                            hi[q] = (unsigned)__bfloat16_as_ushort(h0) |
                                    ((unsigned)__bfloat16_as_ushort(h1) << 16);
                            lo[q] = (unsigned)__bfloat16_as_ushort(l0) |
                                    ((unsigned)__bfloat16_as_ushort(l1) << 16);
                        }
                        int jt = j0 >> 6, jc = j0 & 63;
                        unsigned off = SWZ(row * 128 + jc * 2);
                        *reinterpret_cast<uint4*>(smem + AHI + jt * 16384 + off) =
                            make_uint4(hi[0], hi[1], hi[2], hi[3]);
                        *reinterpret_cast<uint4*>(smem + ALO + jt * 16384 + off) =
                            make_uint4(lo[0], lo[1], lo[2], lo[3]);
                    }
                }
                TC_FENCE_BEFORE();
            }
            __syncthreads();
        }
        if (HALVES == 2) {   // rebuild A tiles kt 0,1 (units 0..127) from out (L2-hot)
            for (int i = tid; i < 128 * 16; i += 256) {
                int row = i >> 4, j0 = (i & 15) * 8;
                const float* orow =
                    out + ((size_t)(b0 + row) * TT + t) * (2 * U) + (size_t)dir * U;
                float4 a = *reinterpret_cast<const float4*>(orow + j0);
                float4 b4 = *reinterpret_cast<const float4*>(orow + j0 + 4);
                float hv[8] = {a.x, a.y, a.z, a.w, b4.x, b4.y, b4.z, b4.w};
                unsigned hi[4], lo[4];
#pragma unroll
                for (int q = 0; q < 4; ++q) {
                    __nv_bfloat16 h0, l0, h1, l1;
                    bfsplit(hv[2 * q], h0, l0);
                    bfsplit(hv[2 * q + 1], h1, l1);
                    hi[q] = (unsigned)__bfloat16_as_ushort(h0) |
                            ((unsigned)__bfloat16_as_ushort(h1) << 16);
                    lo[q] = (unsigned)__bfloat16_as_ushort(l0) |
                            ((unsigned)__bfloat16_as_ushort(l1) << 16);
                }
                int jt = j0 >> 6, jc = j0 & 63;
                unsigned off = SWZ(row * 128 + jc * 2);
                *reinterpret_cast<uint4*>(smem + AHI + jt * 16384 + off) =
                    make_uint4(hi[0], hi[1], hi[2], hi[3]);
                *reinterpret_cast<uint4*>(smem + ALO + jt * 16384 + off) =
                    make_uint4(lo[0], lo[1], lo[2], lo[3]);
            }
        }
        FENCE_ASYNC();
        __syncthreads();
    }
    if (wid == 0) TC_DEALLOC(tmem, TMC);
#else
    // naive fallback (never the executing cubin; correct + compilable)
    (void)Uhi; (void)Ulo;
    float* hs = reinterpret_cast<float*>(smem);   // [128][U]
    for (int i = tid; i < 128 * U; i += 256) hs[i] = 0.f;
    __syncthreads();
    const float* Uw = dir ? Ub_raw : Uf_raw;      // [U][4U]
    for (int step = 0; step < TT; ++step) {
        const int t = dir ? (TT - 1 - step) : step;
        if (tid < 128) {
            const int row = tid;
            const size_t m = (size_t)(b0 + row) * TT + t;
            float* crow = cst + ((size_t)dir * BATCH + b0 + row) * U;
            float* orow = out + m * (2 * U) + (size_t)dir * U;
            for (int j = 0; j < U; ++j) {
                float z[4];
                for (int g = 0; g < 4; ++g) {
                    float a = xzd[m * NALL + j * 4 + g];
                    for (int k = 0; k < U; ++k)
                        a += hs[row * U + k] * Uw[(size_t)k * 4 * U + g * U + j];
                    z[g] = a;
                }
                float co = step ? crow[j] : 0.f;
                float c2 = sigf(z[1]) * co + sigf(z[0]) * reluf(z[2]);
                float h = sigf(z[3]) * reluf(c2);
                crow[j] = c2; orow[j] = h;
            }
        }
        __syncthreads();
        if (tid < 128) {
            const size_t m = (size_t)(b0 + tid) * TT + t;
            for (int j = 0; j < U; ++j)
                hs[tid * U + j] = out[m * (2 * U) + (size_t)dir * U + j];
        }
        __syncthreads();
    }
#endif
}

// ================= tail =================
__global__ void __launch_bounds__(128) tail_kernel(
    const float* __restrict__ H1,
    const float* __restrict__ W2, const float* __restrict__ B2,
    const float* __restrict__ W3, const float* __restrict__ B3,
    const float* __restrict__ G, const float* __restrict__ Bb,
    const float* __restrict__ M, const float* __restrict__ V,
    const float* __restrict__ WO, const float* __restrict__ BO,
    float* __restrict__ Out) {
    __shared__ float h1s[4][256];
    __shared__ float h2s[4][128];
    __shared__ float h3s[4][64];
    int tid = threadIdx.x, lane = tid & 31, w = tid >> 5;
    int r0 = blockIdx.x * 4;
    for (int i = tid; i < 4 * 256; i += 128) h1s[i >> 8][i & 255] = H1[(size_t)r0 * 256 + i];
    __syncthreads();
    {
        int j = lane * 4;
        float4 bv = *reinterpret_cast<const float4*>(&B2[j]);
        float a0 = bv.x, a1 = bv.y, a2 = bv.z, a3 = bv.w;
#pragma unroll 4
        for (int k = 0; k < 256; k++) {
            float a = h1s[w][k];
            float4 wv = *reinterpret_cast<const float4*>(&W2[(size_t)k * 128 + j]);
            a0 += a * wv.x; a1 += a * wv.y; a2 += a * wv.z; a3 += a * wv.w;
        }
        h2s[w][j] = reluf(a0); h2s[w][j + 1] = reluf(a1);
        h2s[w][j + 2] = reluf(a2); h2s[w][j + 3] = reluf(a3);
    }
    __syncwarp();
    {
        int j = lane * 2;
        float a0 = B3[j], a1 = B3[j + 1];
#pragma unroll 4
        for (int k = 0; k < 128; k++) {
            float a = h2s[w][k];
            float2 wv = *reinterpret_cast<const float2*>(&W3[(size_t)k * 64 + j]);
            a0 += a * wv.x; a1 += a * wv.y;
        }
        a0 = reluf(a0); a1 = reluf(a1);
        float s0 = rsqrtf(V[j] + 1e-3f) * G[j];
        float s1 = rsqrtf(V[j + 1] + 1e-3f) * G[j + 1];
        h3s[w][j]     = (a0 - M[j]) * s0 + Bb[j];
        h3s[w][j + 1] = (a1 - M[j + 1]) * s1 + Bb[j + 1];
    }
    __syncwarp();
    float logit = -3.0e38f;
    if (lane < 26) {
        float a = BO[lane];
#pragma unroll 4
        for (int k = 0; k < 64; k++) a += h3s[w][k] * WO[(size_t)k * 26 + lane];
        logit = a;
    }
    float mx = logit;
#pragma unroll
    for (int o = 16; o; o >>= 1) mx = fmaxf(mx, __shfl_xor_sync(0xffffffffu, mx, o));
    float e = (lane < 26) ? __expf(logit - mx) : 0.f;
    float s = e;
#pragma unroll
    for (int o = 16; o; o >>= 1) s += __shfl_xor_sync(0xffffffffu, s, o);
    if (lane < 26) Out[(size_t)(r0 + w) * 26 + lane] = e * __fdividef(1.f, s);
}

// ================= launch =================
extern "C" void kernel_launch(void* const* d_in, const int* in_sizes, int n_in,
                              void* d_out, int out_size) {
    const float* x   = (const float*)d_in[0];
    const float* w1f = (const float*)d_in[1];
    const float* u1f = (const float*)d_in[2];
    const float* b1f = (const float*)d_in[3];
    const float* w1b = (const float*)d_in[4];
    const float* u1b = (const float*)d_in[5];
    const float* b1b = (const float*)d_in[6];
    const float* w2f = (const float*)d_in[7];
    const float* u2f = (const float*)d_in[8];
    const float* b2f = (const float*)d_in[9];
    const float* w2b = (const float*)d_in[10];
    const float* u2b = (const float*)d_in[11];
    const float* b2b = (const float*)d_in[12];
    const float* w3f = (const float*)d_in[13];
    const float* u3f = (const float*)d_in[14];
    const float* b3f = (const float*)d_in[15];
    const float* w3b = (const float*)d_in[16];
    const float* u3b = (const float*)d_in[17];
    const float* b3b = (const float*)d_in[18];
    const float* d1w = (const float*)d_in[19];
    const float* d1b = (const float*)d_in[20];
    const float* d2w = (const float*)d_in[21];
    const float* d2b = (const float*)d_in[22];
    const float* d3w = (const float*)d_in[23];
    const float* d3b = (const float*)d_in[24];
    const float* bng = (const float*)d_in[25];
    const float* bnb = (const float*)d_in[26];
    const float* bnm = (const float*)d_in[27];
    const float* bnv = (const float*)d_in[28];
    const float* ow  = (const float*)d_in[29];
    const float* ob  = (const float*)d_in[30];

    float *bufA, *bufB, *h1, *xz, *cst, *bg1, *bg2, *bg3;
    __nv_bfloat16 *uh1, *ul1, *uh2, *ul2, *uh3, *ul3;
    __nv_bfloat16 *w1h, *w1l, *w2h, *w2l, *w3h, *w3l, *wdh, *wdl;
    cudaGetSymbolAddress((void**)&bufA, g_bufA);
    cudaGetSymbolAddress((void**)&bufB, g_bufB);
    cudaGetSymbolAddress((void**)&h1, g_h1);
    cudaGetSymbolAddress((void**)&xz, g_xz);
    cudaGetSymbolAddress((void**)&cst, g_c);
    cudaGetSymbolAddress((void**)&bg1, g_bg1);
    cudaGetSymbolAddress((void**)&bg2, g_bg2);
    cudaGetSymbolAddress((void**)&bg3, g_bg3);
    cudaGetSymbolAddress((void**)&uh1, g_uh1);
    cudaGetSymbolAddress((void**)&ul1, g_ul1);
    cudaGetSymbolAddress((void**)&uh2, g_uh2);
    cudaGetSymbolAddress((void**)&ul2, g_ul2);
    cudaGetSymbolAddress((void**)&uh3, g_uh3);
    cudaGetSymbolAddress((void**)&ul3, g_ul3);
    cudaGetSymbolAddress((void**)&w1h, g_w1h);
    cudaGetSymbolAddress((void**)&w1l, g_w1l);
    cudaGetSymbolAddress((void**)&w2h, g_w2h);
    cudaGetSymbolAddress((void**)&w2l, g_w2l);
    cudaGetSymbolAddress((void**)&w3h, g_w3h);
    cudaGetSymbolAddress((void**)&w3l, g_w3l);
    cudaGetSymbolAddress((void**)&wdh, g_wdh);
    cudaGetSymbolAddress((void**)&wdl, g_wdl);

    cudaFuncSetAttribute(gemm_kernel<false>, cudaFuncAttributeMaxDynamicSharedMemorySize, SMEMG);
    cudaFuncSetAttribute(gemm_kernel<true>,  cudaFuncAttributeMaxDynamicSharedMemorySize, SMEMG);
    const int r1 = 1024 + 2 * 16384 + 65536;   // 99328
    const int r2 = 1024 + 4 * 16384 + 65536;   // 132096
    const int r3 = 1024 + 8 * 16384 + 65536;   // 197632
    cudaFuncSetAttribute(lstm_rec_tc<64>,  cudaFuncAttributeMaxDynamicSharedMemorySize, r1);
    cudaFuncSetAttribute(lstm_rec_tc<128>, cudaFuncAttributeMaxDynamicSharedMemorySize, r2);
    cudaFuncSetAttribute(lstm_rec_tc<256>, cudaFuncAttributeMaxDynamicSharedMemorySize, r3);

    prep_lstm<<<512, 256>>>(u1f, u1b, u2f, u2b, u3f, u3b,
                            w1f, w1b, w2f, w2b, w3f, w3b,
                            b1f, b1b, b2f, b2b, b3f, b3b);
    prep_dense<<<512, 256>>>(d1w);

    // L1
    gemm_kernel<false><<<dim3(MBT / 128, 1, 2), 256, SMEMG>>>(
        x, w1h, w1l, bg1, xz, 126, 128, 256, (size_t)MBT * 256);
    lstm_rec_tc<64><<<dim3(BATCH / 128, 2), 256, r1>>>(xz, uh1, ul1, u1f, u1b, cst, bufA);
    // L2
    gemm_kernel<false><<<dim3(MBT / 128, 2, 2), 256, SMEMG>>>(
        bufA, w2h, w2l, bg2, xz, 128, 128, 512, (size_t)MBT * 512);
    lstm_rec_tc<128><<<dim3(BATCH / 128, 2), 256, r2>>>(xz, uh2, ul2, u2f, u2b, cst, bufB);
    // L3
    gemm_kernel<false><<<dim3(MBT / 128, 4, 2), 256, SMEMG>>>(
        bufB, w3h, w3l, bg3, xz, 256, 256, 1024, (size_t)MBT * 1024);
    lstm_rec_tc<256><<<dim3(BATCH / 128, 2), 256, r3>>>(xz, uh3, ul3, u3f, u3b, cst, bufA);
    // dense1 (M=8192, K=15360, N=256) + relu
    gemm_kernel<true><<<dim3(BATCH / 128, 1, 1), 256, SMEMG>>>(
        bufA, wdh, wdl, d1b, h1, 15360, 15360, 256, 0);
    tail_kernel<<<BATCH / 4, 128>>>(h1, d2w, d2b, d3w, d3b, bng, bnb, bnm, bnv, ow, ob,
                                    (float*)d_out);
    (void)in_sizes; (void)n_in; (void)out_size;
}